// round 13
// baseline (speedup 1.0000x reference)
#include <cuda_runtime.h>
#include <cuda_fp16.h>
#include <math.h>
#include <stdint.h>

// Problem constants
#define BB    8192
#define DIN   2048
#define MM    1600
#define CC    20
#define SS    80
#define OUTN  3000

// ---------------------------------------------------------------------------
// Scratch (static device globals)
// ---------------------------------------------------------------------------
__device__ float g_h0[(size_t)BB * MM];
__device__ float g_zT[(size_t)MM * BB];

__device__ __half g_x0h[(size_t)BB * DIN];
__device__ __half g_x1h[(size_t)BB * DIN];
__device__ __half g_W0h[(size_t)MM * DIN];
__device__ __half g_W1h[(size_t)MM * DIN];
__device__ __half g_Wouth[(size_t)OUTN * MM];
__device__ __half g_Wbh[(size_t)CC * SS * SS * SS];
__device__ __half g_h1h[(size_t)BB * MM];
__device__ __half g_zh[(size_t)BB * MM];

// ---------------------------------------------------------------------------
// Low-level helpers
// ---------------------------------------------------------------------------
__device__ __forceinline__ uint32_t smem_u32(const void* p) {
    uint32_t a;
    asm("{ .reg .u64 t; cvta.to.shared.u64 t, %1; cvt.u32.u64 %0, t; }"
        : "=r"(a) : "l"(p));
    return a;
}

#define CP16(dst, src) \
    asm volatile("cp.async.cg.shared.global [%0], [%1], 16;" \
                 :: "r"(dst), "l"(src) : "memory")
#define CP16P(dst, src, nbytes) \
    asm volatile("cp.async.cg.shared.global [%0], [%1], 16, %2;" \
                 :: "r"(dst), "l"(src), "r"(nbytes) : "memory")
#define CP_COMMIT() asm volatile("cp.async.commit_group;" ::: "memory")
#define CP_WAIT0()  asm volatile("cp.async.wait_group 0;" ::: "memory")
#define CP_WAIT1()  asm volatile("cp.async.wait_group 1;" ::: "memory")

#define LDX4(r0, r1, r2, r3, addr) \
    asm volatile("ldmatrix.sync.aligned.m8n8.x4.shared.b16 {%0,%1,%2,%3}, [%4];" \
                 : "=r"(r0), "=r"(r1), "=r"(r2), "=r"(r3) : "r"(addr))

#define MMAH(d0, d1, d2, d3, a0, a1, a2, a3, b0, b1) \
    asm volatile("mma.sync.aligned.m16n8k16.row.col.f32.f16.f16.f32 " \
                 "{%0,%1,%2,%3}, {%4,%5,%6,%7}, {%8,%9}, {%0,%1,%2,%3};" \
                 : "+f"(d0), "+f"(d1), "+f"(d2), "+f"(d3) \
                 : "r"(a0), "r"(a1), "r"(a2), "r"(a3), "r"(b0), "r"(b1))

// ---------------------------------------------------------------------------
// fp32 -> fp16 converts (paired, independent sizes per grid.y)
// ---------------------------------------------------------------------------
__global__ __launch_bounds__(256)
void cvt2_fp16(const float* __restrict__ in0, __half* __restrict__ out0, int n4a,
               const float* __restrict__ in1, __half* __restrict__ out1, int n4b)
{
    int i = blockIdx.x * blockDim.x + threadIdx.x;
    const float* in = blockIdx.y ? in1 : in0;
    __half* out = blockIdx.y ? out1 : out0;
    int n4 = blockIdx.y ? n4b : n4a;
    if (i >= n4) return;
    float4 v = ((const float4*)in)[i];
    __half2 a = __halves2half2(__float2half(v.x), __float2half(v.y));
    __half2 b = __halves2half2(__float2half(v.z), __float2half(v.w));
    uint2 o;
    o.x = *(uint32_t*)&a; o.y = *(uint32_t*)&b;
    ((uint2*)out)[i] = o;
}

// ---------------------------------------------------------------------------
// 1-product fp16 NT GEMM core: CTA 128x128xBK64, 3-stage, 2 CTAs/SM,
// 256 threads (8 warps, warp tile 64x32), single sync per K-iter.  [R11 cfg]
// ---------------------------------------------------------------------------
#define BK 64
#define STG1 32768            // A 16K | B 16K
#define SMEM1 (3 * STG1)      // 96K

__device__ __forceinline__ void issue1(
    uint32_t sbase, int stage,
    const __half* __restrict__ A, const __half* __restrict__ B,
    int m0, int n0, int k0, int N, int K, int tid)
{
    uint32_t st = sbase + stage * STG1;
#pragma unroll
    for (int i = 0; i < 4; ++i) {
        int idx = tid + i * 256;
        int r = idx >> 3;
        int c = idx & 7;
        uint32_t dst = (uint32_t)(r * 128 + ((c ^ (r & 7)) << 4));
        CP16(st + dst, (const char*)(A + (size_t)(m0 + r) * K + k0 + c * 8));
        int n = n0 + r;
        int pred = (n < N) ? 16 : 0;
        int ncl = (n < N) ? n : (N - 1);
        CP16P(st + 16384 + dst, (const char*)(B + (size_t)ncl * K + k0 + c * 8), pred);
    }
    CP_COMMIT();
}

__device__ __forceinline__ void gemm1_mainloop(
    uint32_t sb, const __half* A, const __half* B,
    int m0, int n0, int N, int K, int tid, float d[4][4][4])
{
    const int l   = tid & 31;
    const int wid = tid >> 5;
    const int wm  = wid & 1;
    const int wn  = wid >> 1;
    const int niter = K / BK;

    const uint32_t aRow  = (uint32_t)(wm * 64 + (l & 15));
    const uint32_t aXor  = aRow & 7;
    const uint32_t aHalf = (uint32_t)(l >> 4);
    const uint32_t bRow  = (uint32_t)(wn * 32 + (l & 7) + ((l >> 4) << 3));
    const uint32_t bXor  = bRow & 7;
    const uint32_t bHalf = (uint32_t)((l >> 3) & 1);

    issue1(sb, 0, A, B, m0, n0, 0, N, K, tid);
    if (niter > 1) issue1(sb, 1, A, B, m0, n0, BK, N, K, tid);

    for (int it = 0; it < niter; ++it) {
        if (it + 1 < niter) CP_WAIT1(); else CP_WAIT0();
        __syncthreads();
        if (it + 2 < niter)
            issue1(sb, (it + 2) % 3, A, B, m0, n0, (it + 2) * BK, N, K, tid);

        const uint32_t st = sb + (it % 3) * STG1;
        const uint32_t sA = st;
        const uint32_t sB = st + 16384;

#pragma unroll
        for (int kk = 0; kk < 4; ++kk) {
            uint32_t ah[4][4], bh[2][4];
            const uint32_t ach = (((2 * kk + aHalf) ^ aXor) << 4);
            const uint32_t bch = (((2 * kk + bHalf) ^ bXor) << 4);
#pragma unroll
            for (int mg = 0; mg < 4; ++mg) {
                uint32_t off = (aRow + mg * 16) * 128 + ach;
                LDX4(ah[mg][0], ah[mg][1], ah[mg][2], ah[mg][3], sA + off);
            }
#pragma unroll
            for (int bq = 0; bq < 2; ++bq) {
                uint32_t off = (bRow + bq * 16) * 128 + bch;
                LDX4(bh[bq][0], bh[bq][1], bh[bq][2], bh[bq][3], sB + off);
            }
#pragma unroll
            for (int mg = 0; mg < 4; ++mg) {
#pragma unroll
                for (int bq = 0; bq < 2; ++bq) {
#pragma unroll
                    for (int hh = 0; hh < 2; ++hh) {
                        float* dd = d[mg][bq * 2 + hh];
                        MMAH(dd[0], dd[1], dd[2], dd[3],
                             ah[mg][0], ah[mg][1], ah[mg][2], ah[mg][3],
                             bh[bq][2 * hh], bh[bq][2 * hh + 1]);
                    }
                }
            }
        }
    }
}

// Merged input GEMMs: blockIdx.z=0 -> h0 fp32; z=1 -> h1 fp16.
__global__ __launch_bounds__(256, 2)
void tc_gemm_in(const __half* __restrict__ A0, const __half* __restrict__ A1,
                const __half* __restrict__ B0, const __half* __restrict__ B1,
                const float* __restrict__ bias0, const float* __restrict__ bias1,
                float* __restrict__ C0, __half* __restrict__ C1,
                int N, int K)
{
    extern __shared__ __align__(128) char smem[];
    const uint32_t sb = smem_u32(smem);
    const int tid = threadIdx.x;
    const int which = blockIdx.z;
    const int m0 = blockIdx.y * 128;
    const int n0 = blockIdx.x * 128;

    const __half* A   = which ? A1 : A0;
    const __half* B   = which ? B1 : B0;
    const float* bias = which ? bias1 : bias0;

    float d[4][4][4];
#pragma unroll
    for (int mg = 0; mg < 4; ++mg)
#pragma unroll
        for (int ng = 0; ng < 4; ++ng)
#pragma unroll
            for (int e = 0; e < 4; ++e) d[mg][ng][e] = 0.0f;

    gemm1_mainloop(sb, A, B, m0, n0, N, K, tid, d);

    const int l  = tid & 31;
    const int wm = (tid >> 5) & 1;
    const int wn = tid >> 6;
#pragma unroll
    for (int mg = 0; mg < 4; ++mg) {
#pragma unroll
        for (int ng = 0; ng < 4; ++ng) {
            int m = m0 + wm * 64 + mg * 16 + (l >> 2);
            int n = n0 + wn * 32 + ng * 8 + 2 * (l & 3);
            if (n < N) {
                float v0 = d[mg][ng][0] + bias[n];
                float v1 = d[mg][ng][1] + bias[n + 1];
                float v2 = d[mg][ng][2] + bias[n];
                float v3 = d[mg][ng][3] + bias[n + 1];
                if (!which) {
                    *(float2*)&C0[(size_t)m * N + n] = make_float2(v0, v1);
                    *(float2*)&C0[(size_t)(m + 8) * N + n] = make_float2(v2, v3);
                } else {
                    *(__half2*)&C1[(size_t)m * N + n] =
                        __halves2half2(__float2half(v0), __float2half(v1));
                    *(__half2*)&C1[(size_t)(m + 8) * N + n] =
                        __halves2half2(__float2half(v2), __float2half(v3));
                }
            }
        }
    }
}

// Out GEMM: fp32 output
__global__ __launch_bounds__(256, 2)
void tc_gemm_out(const __half* __restrict__ A, const __half* __restrict__ B,
                 const float* __restrict__ bias, float* __restrict__ C,
                 int N, int K)
{
    extern __shared__ __align__(128) char smem[];
    const uint32_t sb = smem_u32(smem);
    const int tid = threadIdx.x;
    const int m0 = blockIdx.y * 128;
    const int n0 = blockIdx.x * 128;

    float d[4][4][4];
#pragma unroll
    for (int mg = 0; mg < 4; ++mg)
#pragma unroll
        for (int ng = 0; ng < 4; ++ng)
#pragma unroll
            for (int e = 0; e < 4; ++e) d[mg][ng][e] = 0.0f;

    gemm1_mainloop(sb, A, B, m0, n0, N, K, tid, d);

    const int l  = tid & 31;
    const int wm = (tid >> 5) & 1;
    const int wn = tid >> 6;
#pragma unroll
    for (int mg = 0; mg < 4; ++mg) {
#pragma unroll
        for (int ng = 0; ng < 4; ++ng) {
            int m = m0 + wm * 64 + mg * 16 + (l >> 2);
            int n = n0 + wn * 32 + ng * 8 + 2 * (l & 3);
            if (n < N) {
                float v0 = d[mg][ng][0] + bias[n];
                float v1 = d[mg][ng][1] + bias[n + 1];
                float v2 = d[mg][ng][2] + bias[n];
                float v3 = d[mg][ng][3] + bias[n + 1];
                *(float2*)&C[(size_t)m * N + n] = make_float2(v0, v1);
                *(float2*)&C[(size_t)(m + 8) * N + n] = make_float2(v2, v3);
            }
        }
    }
}

// ---------------------------------------------------------------------------
// Fused bilinear + bias + signed-sqrt + per-chunk L2 normalize.
// CTA = (c, 256-batch block). h0/h1 loaded once; Wb double-buffered over
// 40 q-pairs. During epilogues: bias added, |z| accumulated in smem
// (per-b sums over all 80 q), raw z+bb written to zT. After the qp loop,
// the CTA re-reads its own zT slice (L2-resident), applies
// signed-sqrt * scale, and writes fp16 zh (staged via smem for coalescing).
// ---------------------------------------------------------------------------
#define WB_PITCH 176
#define H1_PITCH 176
#define H0_PITCHB 336
#define H0_PITCHF 84
#define WB_STAGE 28160
#define SH1 56320
#define SH0 101376
#define SUM_OFF 187392          // 256 floats
#define BBS_OFF 188416          // 80 floats
#define BIL_SMEM 188736

__device__ __forceinline__ void issue_wb(
    uint32_t sb, int buf, const __half* __restrict__ Wbh,
    int c, int qp, int tid)
{
    const size_t wb_base = (size_t)c * (SS * SS * SS) + (size_t)(qp * 2) * (SS * SS);
    uint32_t base = sb + buf * WB_STAGE;
#pragma unroll
    for (int i = 0; i < 7; ++i) {
        int idx = tid + i * 256;
        if (idx < 1600) {
            int row = idx / 10, ch = idx % 10;
            size_t src = wb_base + (size_t)(row / 80) * (SS * SS)
                       + (size_t)(row % 80) * SS + ch * 8;
            CP16(base + row * WB_PITCH + ch * 16, (const char*)(Wbh + src));
        }
    }
    CP_COMMIT();
}

__global__ __launch_bounds__(256, 1)
void bilq_kernel(const __half* __restrict__ Wbh,
                 const __half* __restrict__ h1h,
                 const float* __restrict__ h0g,
                 const float* __restrict__ bbv,
                 float* __restrict__ zT,
                 __half* __restrict__ zh)
{
    extern __shared__ __align__(128) char smem[];
    const uint32_t sb = smem_u32(smem);
    float* sumabs = (float*)(smem + SUM_OFF);
    float* bbs    = (float*)(smem + BBS_OFF);
    const int tid = threadIdx.x;
    const int l   = tid & 31;
    const int wid = tid >> 5;
    const int wm  = wid >> 2;
    const int wn  = wid & 3;
    const int c     = blockIdx.y;
    const int bbase = blockIdx.x * 256;

    sumabs[tid] = 0.0f;
    if (tid < 80) bbs[tid] = bbv[c * SS + tid];

#pragma unroll
    for (int i = 0; i < 10; ++i) {
        int idx = tid + i * 256;
        int r = idx / 10, ch = idx % 10;
        size_t src = (size_t)(bbase + r) * MM + c * SS + ch * 8;
        CP16(sb + SH1 + r * H1_PITCH + ch * 16, (const char*)(h1h + src));
    }
#pragma unroll
    for (int i = 0; i < 20; ++i) {
        int idx = tid + i * 256;
        int r = idx / 20, ch = idx % 20;
        size_t src = (size_t)(bbase + r) * MM + c * SS + ch * 4;
        CP16(sb + SH0 + r * H0_PITCHB + ch * 16, (const char*)(h0g + src));
    }
    issue_wb(sb, 0, Wbh, c, 0, tid);
    issue_wb(sb, 1, Wbh, c, 1, tid);

    const uint32_t aRowOff = (uint32_t)(wm * 80 + (l & 15)) * WB_PITCH;
    const uint32_t aHalf   = (uint32_t)(l >> 4);
    const uint32_t bRowOff = (uint32_t)((l & 7) + ((l >> 4) << 3)) * H1_PITCH;
    const uint32_t bHalf   = (uint32_t)((l >> 3) & 1);

    for (int qp = 0; qp < 40; ++qp) {
        if (qp + 1 < 40) CP_WAIT1(); else CP_WAIT0();
        __syncthreads();
        const uint32_t sA = sb + (qp & 1) * WB_STAGE;

#pragma unroll
        for (int bt = 0; bt < 2; ++bt) {
            const uint32_t sB = sb + SH1 + (uint32_t)(bt * 128) * H1_PITCH;
            const float* h0s = (const float*)(smem + SH0 + bt * 128 * H0_PITCHB);
            const int b0 = bbase + bt * 128;

            float d[5][4][4];
#pragma unroll
            for (int mt = 0; mt < 5; ++mt)
#pragma unroll
                for (int nt = 0; nt < 4; ++nt)
#pragma unroll
                    for (int e = 0; e < 4; ++e) d[mt][nt][e] = 0.0f;

#pragma unroll
            for (int kk = 0; kk < 5; ++kk) {
                uint32_t ah[5][4], bh[2][4];
                const uint32_t aco = ((2 * kk + aHalf) << 4);
                const uint32_t bco = ((2 * kk + bHalf) << 4);
#pragma unroll
                for (int mt = 0; mt < 5; ++mt) {
                    uint32_t off = aRowOff + mt * 16 * WB_PITCH + aco;
                    LDX4(ah[mt][0], ah[mt][1], ah[mt][2], ah[mt][3], sA + off);
                }
#pragma unroll
                for (int pr = 0; pr < 2; ++pr) {
                    uint32_t off = (uint32_t)(wn * 32 + pr * 16) * H1_PITCH
                                 + bRowOff + bco;
                    LDX4(bh[pr][0], bh[pr][1], bh[pr][2], bh[pr][3], sB + off);
                }
#pragma unroll
                for (int mt = 0; mt < 5; ++mt) {
#pragma unroll
                    for (int pr = 0; pr < 2; ++pr) {
#pragma unroll
                        for (int hh = 0; hh < 2; ++hh) {
                            int nt = pr * 2 + hh;
                            float* dd = d[mt][nt];
                            MMAH(dd[0], dd[1], dd[2], dd[3],
                                 ah[mt][0], ah[mt][1], ah[mt][2], ah[mt][3],
                                 bh[pr][2 * hh], bh[pr][2 * hh + 1]);
                        }
                    }
                }
            }

            float p8[8];
#pragma unroll
            for (int i = 0; i < 8; ++i) p8[i] = 0.0f;
#pragma unroll
            for (int mt = 0; mt < 5; ++mt) {
#pragma unroll
                for (int e = 0; e < 4; ++e) {
                    int s = mt * 16 + (l >> 2) + 8 * (e >> 1);
#pragma unroll
                    for (int nt = 0; nt < 4; ++nt) {
                        int bl_ = wn * 32 + nt * 8 + 2 * (l & 3) + (e & 1);
                        p8[nt * 2 + (e & 1)] += d[mt][nt][e] * h0s[bl_ * H0_PITCHF + s];
                    }
                }
            }
#pragma unroll
            for (int pi = 0; pi < 8; ++pi) {
                float v = p8[pi];
                v += __shfl_xor_sync(0xffffffffu, v, 4);
                v += __shfl_xor_sync(0xffffffffu, v, 8);
                v += __shfl_xor_sync(0xffffffffu, v, 16);
                p8[pi] = v;
            }
            if (l < 4) {
                const float bias = bbs[qp * 2 + wm];
                int feat = c * SS + qp * 2 + wm;
                float* dst = zT + (size_t)feat * BB + b0 + wn * 32 + 2 * l;
#pragma unroll
                for (int nt = 0; nt < 4; ++nt) {
                    float v0 = p8[nt * 2] + bias;
                    float v1 = p8[nt * 2 + 1] + bias;
                    *(float2*)(dst + nt * 8) = make_float2(v0, v1);
                    int bl_ = bt * 128 + wn * 32 + nt * 8 + 2 * l;
                    atomicAdd(&sumabs[bl_], fabsf(v0));
                    atomicAdd(&sumabs[bl_ + 1], fabsf(v1));
                }
            }
        }

        __syncthreads();
        if (qp + 2 < 40)
            issue_wb(sb, qp & 1, Wbh, c, qp + 2, tid);
    }

    // ---- fused normalize: signed-sqrt * per-b scale -> fp16 zh ----
    __syncthreads();
    const float sc = 1.0f / fmaxf(sqrtf(sumabs[tid]), 1e-12f);
    __half* zs = (__half*)smem;   // reuse Wb stages: 256 rows x 80 fp16
#pragma unroll 4
    for (int q = 0; q < SS; ++q) {
        float v = zT[(size_t)(c * SS + q) * BB + bbase + tid];
        float sv = copysignf(sqrtf(fabsf(v)), v) * sc;
        zs[tid * SS + q] = __float2half(sv);
    }
    __syncthreads();
#pragma unroll
    for (int i = 0; i < 10; ++i) {
        int idx = tid + i * 256;
        int r = idx / 10, ch = idx % 10;
        uint4 vv = *(uint4*)((char*)zs + r * 160 + ch * 16);
        *(uint4*)&zh[(size_t)(bbase + r) * MM + c * SS + ch * 8] = vv;
    }
}

// ---------------------------------------------------------------------------
// launch
// ---------------------------------------------------------------------------
extern "C" void kernel_launch(void* const* d_in, const int* in_sizes, int n_in,
                              void* d_out, int out_size)
{
    (void)in_sizes; (void)n_in; (void)out_size;
    const float* x0   = (const float*)d_in[0];
    const float* x1   = (const float*)d_in[1];
    const float* W0   = (const float*)d_in[2];
    const float* b0   = (const float*)d_in[3];
    const float* W1   = (const float*)d_in[4];
    const float* b1   = (const float*)d_in[5];
    const float* Wb   = (const float*)d_in[6];
    const float* bb   = (const float*)d_in[7];
    const float* Wout = (const float*)d_in[8];
    const float* bout = (const float*)d_in[9];
    float* out = (float*)d_out;

    float *h0p, *zTp;
    cudaGetSymbolAddress((void**)&h0p, g_h0);
    cudaGetSymbolAddress((void**)&zTp, g_zT);
    void *x0h, *x1h, *W0h, *W1h, *Woh, *Wbh, *h1h, *zh;
    cudaGetSymbolAddress(&x0h, g_x0h);  cudaGetSymbolAddress(&x1h, g_x1h);
    cudaGetSymbolAddress(&W0h, g_W0h);  cudaGetSymbolAddress(&W1h, g_W1h);
    cudaGetSymbolAddress(&Woh, g_Wouth);
    cudaGetSymbolAddress(&Wbh, g_Wbh);
    cudaGetSymbolAddress(&h1h, g_h1h);
    cudaGetSymbolAddress(&zh, g_zh);

    cudaFuncSetAttribute(tc_gemm_in, cudaFuncAttributeMaxDynamicSharedMemorySize, SMEM1);
    cudaFuncSetAttribute(tc_gemm_out, cudaFuncAttributeMaxDynamicSharedMemorySize, SMEM1);
    cudaFuncSetAttribute(bilq_kernel, cudaFuncAttributeMaxDynamicSharedMemorySize, BIL_SMEM);

    // converts (3 launches)
    {
        int n4x = BB * DIN / 4;
        dim3 g((n4x + 255) / 256, 2);
        cvt2_fp16<<<g, 256>>>(x0, (__half*)x0h, n4x, x1, (__half*)x1h, n4x);

        int n4w = MM * DIN / 4;
        dim3 g2((n4w + 255) / 256, 2);
        cvt2_fp16<<<g2, 256>>>(W0, (__half*)W0h, n4w, W1, (__half*)W1h, n4w);

        int n4wb = CC * SS * SS * SS / 4;     // 2,560,000
        int n4wo = OUTN * MM / 4;             // 1,200,000
        int nmax = n4wb > n4wo ? n4wb : n4wo;
        dim3 g3((nmax + 255) / 256, 2);
        cvt2_fp16<<<g3, 256>>>(Wb, (__half*)Wbh, n4wb, Wout, (__half*)Woh, n4wo);
    }

    // merged input GEMMs (1-product)
    {
        dim3 grid((MM + 127) / 128, BB / 128, 2);
        tc_gemm_in<<<grid, 256, SMEM1>>>(
            (const __half*)x0h, (const __half*)x1h,
            (const __half*)W0h, (const __half*)W1h,
            b0, b1, h0p, (__half*)h1h, MM, DIN);
    }

    // fused bilinear + normalize -> zh
    {
        dim3 grid(BB / 256, CC);
        bilq_kernel<<<grid, 256, BIL_SMEM>>>(
            (const __half*)Wbh, (const __half*)h1h, h0p, bb, zTp, (__half*)zh);
    }

    // out = z @ Wout^T + bout (1-product)
    {
        dim3 grid((OUTN + 127) / 128, BB / 128);
        tc_gemm_out<<<grid, 256, SMEM1>>>(
            (const __half*)zh, (const __half*)Woh, bout, out, OUTN, MM);
    }
}

// round 14
// speedup vs baseline: 1.1218x; 1.1218x over previous
#include <cuda_runtime.h>
#include <cuda_fp16.h>
#include <math.h>
#include <stdint.h>

// Problem constants
#define BB    8192
#define DIN   2048
#define MM    1600
#define CC    20
#define SS    80
#define OUTN  3000

// ---------------------------------------------------------------------------
// Scratch (static device globals)
// ---------------------------------------------------------------------------
__device__ float g_h0[(size_t)BB * MM];

__device__ __half g_x0h[(size_t)BB * DIN];
__device__ __half g_x1h[(size_t)BB * DIN];
__device__ __half g_W0h[(size_t)MM * DIN];
__device__ __half g_W1h[(size_t)MM * DIN];
__device__ __half g_Wouth[(size_t)OUTN * MM];
__device__ __half g_Wbh[(size_t)CC * SS * SS * SS];
__device__ __half g_h1h[(size_t)BB * MM];
__device__ __half g_zh[(size_t)BB * MM];

// ---------------------------------------------------------------------------
// Low-level helpers
// ---------------------------------------------------------------------------
__device__ __forceinline__ uint32_t smem_u32(const void* p) {
    uint32_t a;
    asm("{ .reg .u64 t; cvta.to.shared.u64 t, %1; cvt.u32.u64 %0, t; }"
        : "=r"(a) : "l"(p));
    return a;
}

#define CP16(dst, src) \
    asm volatile("cp.async.cg.shared.global [%0], [%1], 16;" \
                 :: "r"(dst), "l"(src) : "memory")
#define CP16P(dst, src, nbytes) \
    asm volatile("cp.async.cg.shared.global [%0], [%1], 16, %2;" \
                 :: "r"(dst), "l"(src), "r"(nbytes) : "memory")
#define CP_COMMIT() asm volatile("cp.async.commit_group;" ::: "memory")
#define CP_WAIT0()  asm volatile("cp.async.wait_group 0;" ::: "memory")
#define CP_WAIT1()  asm volatile("cp.async.wait_group 1;" ::: "memory")

#define LDX4(r0, r1, r2, r3, addr) \
    asm volatile("ldmatrix.sync.aligned.m8n8.x4.shared.b16 {%0,%1,%2,%3}, [%4];" \
                 : "=r"(r0), "=r"(r1), "=r"(r2), "=r"(r3) : "r"(addr))

#define MMAH(d0, d1, d2, d3, a0, a1, a2, a3, b0, b1) \
    asm volatile("mma.sync.aligned.m16n8k16.row.col.f32.f16.f16.f32 " \
                 "{%0,%1,%2,%3}, {%4,%5,%6,%7}, {%8,%9}, {%0,%1,%2,%3};" \
                 : "+f"(d0), "+f"(d1), "+f"(d2), "+f"(d3) \
                 : "r"(a0), "r"(a1), "r"(a2), "r"(a3), "r"(b0), "r"(b1))

// ---------------------------------------------------------------------------
// fp32 -> fp16 converts (paired, independent sizes per grid.y)
// ---------------------------------------------------------------------------
__global__ __launch_bounds__(256)
void cvt2_fp16(const float* __restrict__ in0, __half* __restrict__ out0, int n4a,
               const float* __restrict__ in1, __half* __restrict__ out1, int n4b)
{
    int i = blockIdx.x * blockDim.x + threadIdx.x;
    const float* in = blockIdx.y ? in1 : in0;
    __half* out = blockIdx.y ? out1 : out0;
    int n4 = blockIdx.y ? n4b : n4a;
    if (i >= n4) return;
    float4 v = ((const float4*)in)[i];
    __half2 a = __halves2half2(__float2half(v.x), __float2half(v.y));
    __half2 b = __halves2half2(__float2half(v.z), __float2half(v.w));
    uint2 o;
    o.x = *(uint32_t*)&a; o.y = *(uint32_t*)&b;
    ((uint2*)out)[i] = o;
}

// ---------------------------------------------------------------------------
// 1-product fp16 NT GEMM core: CTA 128x128xBK64, 3-stage, 2 CTAs/SM,
// 256 threads (8 warps, warp tile 64x32), single sync per K-iter.  [R11 cfg]
// ---------------------------------------------------------------------------
#define BK 64
#define STG1 32768            // A 16K | B 16K
#define SMEM1 (3 * STG1)      // 96K

__device__ __forceinline__ void issue1(
    uint32_t sbase, int stage,
    const __half* __restrict__ A, const __half* __restrict__ B,
    int m0, int n0, int k0, int N, int K, int tid)
{
    uint32_t st = sbase + stage * STG1;
#pragma unroll
    for (int i = 0; i < 4; ++i) {
        int idx = tid + i * 256;
        int r = idx >> 3;
        int c = idx & 7;
        uint32_t dst = (uint32_t)(r * 128 + ((c ^ (r & 7)) << 4));
        CP16(st + dst, (const char*)(A + (size_t)(m0 + r) * K + k0 + c * 8));
        int n = n0 + r;
        int pred = (n < N) ? 16 : 0;
        int ncl = (n < N) ? n : (N - 1);
        CP16P(st + 16384 + dst, (const char*)(B + (size_t)ncl * K + k0 + c * 8), pred);
    }
    CP_COMMIT();
}

__device__ __forceinline__ void gemm1_mainloop(
    uint32_t sb, const __half* A, const __half* B,
    int m0, int n0, int N, int K, int tid, float d[4][4][4])
{
    const int l   = tid & 31;
    const int wid = tid >> 5;
    const int wm  = wid & 1;
    const int wn  = wid >> 1;
    const int niter = K / BK;

    const uint32_t aRow  = (uint32_t)(wm * 64 + (l & 15));
    const uint32_t aXor  = aRow & 7;
    const uint32_t aHalf = (uint32_t)(l >> 4);
    const uint32_t bRow  = (uint32_t)(wn * 32 + (l & 7) + ((l >> 4) << 3));
    const uint32_t bXor  = bRow & 7;
    const uint32_t bHalf = (uint32_t)((l >> 3) & 1);

    issue1(sb, 0, A, B, m0, n0, 0, N, K, tid);
    if (niter > 1) issue1(sb, 1, A, B, m0, n0, BK, N, K, tid);

    for (int it = 0; it < niter; ++it) {
        if (it + 1 < niter) CP_WAIT1(); else CP_WAIT0();
        __syncthreads();
        if (it + 2 < niter)
            issue1(sb, (it + 2) % 3, A, B, m0, n0, (it + 2) * BK, N, K, tid);

        const uint32_t st = sb + (it % 3) * STG1;
        const uint32_t sA = st;
        const uint32_t sB = st + 16384;

#pragma unroll
        for (int kk = 0; kk < 4; ++kk) {
            uint32_t ah[4][4], bh[2][4];
            const uint32_t ach = (((2 * kk + aHalf) ^ aXor) << 4);
            const uint32_t bch = (((2 * kk + bHalf) ^ bXor) << 4);
#pragma unroll
            for (int mg = 0; mg < 4; ++mg) {
                uint32_t off = (aRow + mg * 16) * 128 + ach;
                LDX4(ah[mg][0], ah[mg][1], ah[mg][2], ah[mg][3], sA + off);
            }
#pragma unroll
            for (int bq = 0; bq < 2; ++bq) {
                uint32_t off = (bRow + bq * 16) * 128 + bch;
                LDX4(bh[bq][0], bh[bq][1], bh[bq][2], bh[bq][3], sB + off);
            }
#pragma unroll
            for (int mg = 0; mg < 4; ++mg) {
#pragma unroll
                for (int bq = 0; bq < 2; ++bq) {
#pragma unroll
                    for (int hh = 0; hh < 2; ++hh) {
                        float* dd = d[mg][bq * 2 + hh];
                        MMAH(dd[0], dd[1], dd[2], dd[3],
                             ah[mg][0], ah[mg][1], ah[mg][2], ah[mg][3],
                             bh[bq][2 * hh], bh[bq][2 * hh + 1]);
                    }
                }
            }
        }
    }
}

// Merged input GEMMs: blockIdx.z=0 -> h0 fp32; z=1 -> h1 fp16.
__global__ __launch_bounds__(256, 2)
void tc_gemm_in(const __half* __restrict__ A0, const __half* __restrict__ A1,
                const __half* __restrict__ B0, const __half* __restrict__ B1,
                const float* __restrict__ bias0, const float* __restrict__ bias1,
                float* __restrict__ C0, __half* __restrict__ C1,
                int N, int K)
{
    extern __shared__ __align__(128) char smem[];
    const uint32_t sb = smem_u32(smem);
    const int tid = threadIdx.x;
    const int which = blockIdx.z;
    const int m0 = blockIdx.y * 128;
    const int n0 = blockIdx.x * 128;

    const __half* A   = which ? A1 : A0;
    const __half* B   = which ? B1 : B0;
    const float* bias = which ? bias1 : bias0;

    float d[4][4][4];
#pragma unroll
    for (int mg = 0; mg < 4; ++mg)
#pragma unroll
        for (int ng = 0; ng < 4; ++ng)
#pragma unroll
            for (int e = 0; e < 4; ++e) d[mg][ng][e] = 0.0f;

    gemm1_mainloop(sb, A, B, m0, n0, N, K, tid, d);

    const int l  = tid & 31;
    const int wm = (tid >> 5) & 1;
    const int wn = tid >> 6;
#pragma unroll
    for (int mg = 0; mg < 4; ++mg) {
#pragma unroll
        for (int ng = 0; ng < 4; ++ng) {
            int m = m0 + wm * 64 + mg * 16 + (l >> 2);
            int n = n0 + wn * 32 + ng * 8 + 2 * (l & 3);
            if (n < N) {
                float v0 = d[mg][ng][0] + bias[n];
                float v1 = d[mg][ng][1] + bias[n + 1];
                float v2 = d[mg][ng][2] + bias[n];
                float v3 = d[mg][ng][3] + bias[n + 1];
                if (!which) {
                    *(float2*)&C0[(size_t)m * N + n] = make_float2(v0, v1);
                    *(float2*)&C0[(size_t)(m + 8) * N + n] = make_float2(v2, v3);
                } else {
                    *(__half2*)&C1[(size_t)m * N + n] =
                        __halves2half2(__float2half(v0), __float2half(v1));
                    *(__half2*)&C1[(size_t)(m + 8) * N + n] =
                        __halves2half2(__float2half(v2), __float2half(v3));
                }
            }
        }
    }
}

// Out GEMM: fp32 output
__global__ __launch_bounds__(256, 2)
void tc_gemm_out(const __half* __restrict__ A, const __half* __restrict__ B,
                 const float* __restrict__ bias, float* __restrict__ C,
                 int N, int K)
{
    extern __shared__ __align__(128) char smem[];
    const uint32_t sb = smem_u32(smem);
    const int tid = threadIdx.x;
    const int m0 = blockIdx.y * 128;
    const int n0 = blockIdx.x * 128;

    float d[4][4][4];
#pragma unroll
    for (int mg = 0; mg < 4; ++mg)
#pragma unroll
        for (int ng = 0; ng < 4; ++ng)
#pragma unroll
            for (int e = 0; e < 4; ++e) d[mg][ng][e] = 0.0f;

    gemm1_mainloop(sb, A, B, m0, n0, N, K, tid, d);

    const int l  = tid & 31;
    const int wm = (tid >> 5) & 1;
    const int wn = tid >> 6;
#pragma unroll
    for (int mg = 0; mg < 4; ++mg) {
#pragma unroll
        for (int ng = 0; ng < 4; ++ng) {
            int m = m0 + wm * 64 + mg * 16 + (l >> 2);
            int n = n0 + wn * 32 + ng * 8 + 2 * (l & 3);
            if (n < N) {
                float v0 = d[mg][ng][0] + bias[n];
                float v1 = d[mg][ng][1] + bias[n + 1];
                float v2 = d[mg][ng][2] + bias[n];
                float v3 = d[mg][ng][3] + bias[n + 1];
                *(float2*)&C[(size_t)m * N + n] = make_float2(v0, v1);
                *(float2*)&C[(size_t)(m + 8) * N + n] = make_float2(v2, v3);
            }
        }
    }
}

// ---------------------------------------------------------------------------
// Fused bilinear + bias + signed-sqrt + per-chunk L2 normalize (no atomics,
// no zT round-trip). CTA = (c, 128-batch block). h0/h1 loaded once; Wb
// double-buffered over 40 q-pairs. Epilogue lanes write z+bb into an smem
// z-buffer [128 b][84 pitch]. After the loop each of 128 threads sums |z|
// over its own row (q ascending, matching old norm order), applies
// signed-sqrt * scale, stages fp16 in smem, then coalesced zh store.
// ---------------------------------------------------------------------------
#define WB_PITCH 176
#define H1_PITCH 176
#define H0_PITCHB 336
#define H0_PITCHF 84
#define WB_STAGE 28160
#define SH1 56320            // h1: 128*176 = 22528
#define SH0 78848            // h0: 128*336 = 43008
#define SZ  121856           // z: 128*84*4 = 43008
#define BBS_OFF 164864       // 80 floats
#define BIL_SMEM 165248

__device__ __forceinline__ void issue_wb(
    uint32_t sb, int buf, const __half* __restrict__ Wbh,
    int c, int qp, int tid)
{
    const size_t wb_base = (size_t)c * (SS * SS * SS) + (size_t)(qp * 2) * (SS * SS);
    uint32_t base = sb + buf * WB_STAGE;
#pragma unroll
    for (int i = 0; i < 7; ++i) {
        int idx = tid + i * 256;
        if (idx < 1600) {
            int row = idx / 10, ch = idx % 10;
            size_t src = wb_base + (size_t)(row / 80) * (SS * SS)
                       + (size_t)(row % 80) * SS + ch * 8;
            CP16(base + row * WB_PITCH + ch * 16, (const char*)(Wbh + src));
        }
    }
    CP_COMMIT();
}

__global__ __launch_bounds__(256, 1)
void bilq_kernel(const __half* __restrict__ Wbh,
                 const __half* __restrict__ h1h,
                 const float* __restrict__ h0g,
                 const float* __restrict__ bbv,
                 __half* __restrict__ zh)
{
    extern __shared__ __align__(128) char smem[];
    const uint32_t sb = smem_u32(smem);
    float* zsm = (float*)(smem + SZ);
    float* bbs = (float*)(smem + BBS_OFF);
    const int tid = threadIdx.x;
    const int l   = tid & 31;
    const int wid = tid >> 5;
    const int wm  = wid >> 2;      // q within pair
    const int wn  = wid & 3;       // 32-b group
    const int c     = blockIdx.y;
    const int bbase = blockIdx.x * 128;

    if (tid < 80) bbs[tid] = bbv[c * SS + tid];

    // ---- prologue: h1, h0 (once), Wb groups 0 and 1 ----
#pragma unroll
    for (int i = 0; i < 5; ++i) {
        int idx = tid + i * 256;      // 1280 = 128 rows x 10 chunks
        int r = idx / 10, ch = idx % 10;
        size_t src = (size_t)(bbase + r) * MM + c * SS + ch * 8;
        CP16(sb + SH1 + r * H1_PITCH + ch * 16, (const char*)(h1h + src));
    }
#pragma unroll
    for (int i = 0; i < 10; ++i) {
        int idx = tid + i * 256;      // 2560 = 128 rows x 20 chunks
        int r = idx / 20, ch = idx % 20;
        size_t src = (size_t)(bbase + r) * MM + c * SS + ch * 4;
        CP16(sb + SH0 + r * H0_PITCHB + ch * 16, (const char*)(h0g + src));
    }
    issue_wb(sb, 0, Wbh, c, 0, tid);
    issue_wb(sb, 1, Wbh, c, 1, tid);

    const uint32_t aRowOff = (uint32_t)(wm * 80 + (l & 15)) * WB_PITCH;
    const uint32_t aHalf   = (uint32_t)(l >> 4);
    const uint32_t bRowOff = (uint32_t)((l & 7) + ((l >> 4) << 3)) * H1_PITCH;
    const uint32_t bHalf   = (uint32_t)((l >> 3) & 1);
    const uint32_t sB = sb + SH1;
    const float* h0s = (const float*)(smem + SH0);

    for (int qp = 0; qp < 40; ++qp) {
        if (qp + 1 < 40) CP_WAIT1(); else CP_WAIT0();
        __syncthreads();
        const uint32_t sA = sb + (qp & 1) * WB_STAGE;

        float d[5][4][4];
#pragma unroll
        for (int mt = 0; mt < 5; ++mt)
#pragma unroll
            for (int nt = 0; nt < 4; ++nt)
#pragma unroll
                for (int e = 0; e < 4; ++e) d[mt][nt][e] = 0.0f;

#pragma unroll
        for (int kk = 0; kk < 5; ++kk) {
            uint32_t ah[5][4], bh[2][4];
            const uint32_t aco = ((2 * kk + aHalf) << 4);
            const uint32_t bco = ((2 * kk + bHalf) << 4);
#pragma unroll
            for (int mt = 0; mt < 5; ++mt) {
                uint32_t off = aRowOff + mt * 16 * WB_PITCH + aco;
                LDX4(ah[mt][0], ah[mt][1], ah[mt][2], ah[mt][3], sA + off);
            }
#pragma unroll
            for (int pr = 0; pr < 2; ++pr) {
                uint32_t off = (uint32_t)(wn * 32 + pr * 16) * H1_PITCH
                             + bRowOff + bco;
                LDX4(bh[pr][0], bh[pr][1], bh[pr][2], bh[pr][3], sB + off);
            }
#pragma unroll
            for (int mt = 0; mt < 5; ++mt) {
#pragma unroll
                for (int pr = 0; pr < 2; ++pr) {
#pragma unroll
                    for (int hh = 0; hh < 2; ++hh) {
                        int nt = pr * 2 + hh;
                        float* dd = d[mt][nt];
                        MMAH(dd[0], dd[1], dd[2], dd[3],
                             ah[mt][0], ah[mt][1], ah[mt][2], ah[mt][3],
                             bh[pr][2 * hh], bh[pr][2 * hh + 1]);
                    }
                }
            }
        }

        // fused fp32 s-contraction epilogue -> smem z buffer
        float p8[8];
#pragma unroll
        for (int i = 0; i < 8; ++i) p8[i] = 0.0f;
#pragma unroll
        for (int mt = 0; mt < 5; ++mt) {
#pragma unroll
            for (int e = 0; e < 4; ++e) {
                int s = mt * 16 + (l >> 2) + 8 * (e >> 1);
#pragma unroll
                for (int nt = 0; nt < 4; ++nt) {
                    int bl_ = wn * 32 + nt * 8 + 2 * (l & 3) + (e & 1);
                    p8[nt * 2 + (e & 1)] += d[mt][nt][e] * h0s[bl_ * H0_PITCHF + s];
                }
            }
        }
#pragma unroll
        for (int pi = 0; pi < 8; ++pi) {
            float v = p8[pi];
            v += __shfl_xor_sync(0xffffffffu, v, 4);
            v += __shfl_xor_sync(0xffffffffu, v, 8);
            v += __shfl_xor_sync(0xffffffffu, v, 16);
            p8[pi] = v;
        }
        if (l < 4) {
            const float bias = bbs[qp * 2 + wm];
            const int q = qp * 2 + wm;
#pragma unroll
            for (int nt = 0; nt < 4; ++nt) {
                int bl_ = wn * 32 + nt * 8 + 2 * l;
                zsm[bl_ * H0_PITCHF + q]       = p8[nt * 2] + bias;
                zsm[(bl_ + 1) * H0_PITCHF + q] = p8[nt * 2 + 1] + bias;
            }
        }

        __syncthreads();
        if (qp + 2 < 40)
            issue_wb(sb, qp & 1, Wbh, c, qp + 2, tid);
    }

    // ---- fused normalize: per-b |z| sum (q ascending), signed-sqrt*scale ----
    __half* zstage = (__half*)smem;    // reuse Wb stages: 128 rows x 80 fp16
    if (tid < 128) {
        const float* zr = &zsm[tid * H0_PITCHF];
        float s = 0.0f;
#pragma unroll 4
        for (int q = 0; q < SS; ++q) s += fabsf(zr[q]);
        const float sc = 1.0f / fmaxf(sqrtf(s), 1e-12f);
#pragma unroll 4
        for (int q = 0; q < SS; ++q) {
            float v = zr[q];
            zstage[tid * SS + q] = __float2half(copysignf(sqrtf(fabsf(v)), v) * sc);
        }
    }
    __syncthreads();
#pragma unroll
    for (int i = 0; i < 5; ++i) {
        int idx = tid + i * 256;      // 1280 = 128 rows x 10 x 16B
        int r = idx / 10, ch = idx % 10;
        uint4 vv = *(uint4*)((char*)zstage + r * 160 + ch * 16);
        *(uint4*)&zh[(size_t)(bbase + r) * MM + c * SS + ch * 8] = vv;
    }
}

// ---------------------------------------------------------------------------
// launch
// ---------------------------------------------------------------------------
extern "C" void kernel_launch(void* const* d_in, const int* in_sizes, int n_in,
                              void* d_out, int out_size)
{
    (void)in_sizes; (void)n_in; (void)out_size;
    const float* x0   = (const float*)d_in[0];
    const float* x1   = (const float*)d_in[1];
    const float* W0   = (const float*)d_in[2];
    const float* b0   = (const float*)d_in[3];
    const float* W1   = (const float*)d_in[4];
    const float* b1   = (const float*)d_in[5];
    const float* Wb   = (const float*)d_in[6];
    const float* bb   = (const float*)d_in[7];
    const float* Wout = (const float*)d_in[8];
    const float* bout = (const float*)d_in[9];
    float* out = (float*)d_out;

    float* h0p;
    cudaGetSymbolAddress((void**)&h0p, g_h0);
    void *x0h, *x1h, *W0h, *W1h, *Woh, *Wbh, *h1h, *zh;
    cudaGetSymbolAddress(&x0h, g_x0h);  cudaGetSymbolAddress(&x1h, g_x1h);
    cudaGetSymbolAddress(&W0h, g_W0h);  cudaGetSymbolAddress(&W1h, g_W1h);
    cudaGetSymbolAddress(&Woh, g_Wouth);
    cudaGetSymbolAddress(&Wbh, g_Wbh);
    cudaGetSymbolAddress(&h1h, g_h1h);
    cudaGetSymbolAddress(&zh, g_zh);

    cudaFuncSetAttribute(tc_gemm_in, cudaFuncAttributeMaxDynamicSharedMemorySize, SMEM1);
    cudaFuncSetAttribute(tc_gemm_out, cudaFuncAttributeMaxDynamicSharedMemorySize, SMEM1);
    cudaFuncSetAttribute(bilq_kernel, cudaFuncAttributeMaxDynamicSharedMemorySize, BIL_SMEM);

    // converts (3 launches)
    {
        int n4x = BB * DIN / 4;
        dim3 g((n4x + 255) / 256, 2);
        cvt2_fp16<<<g, 256>>>(x0, (__half*)x0h, n4x, x1, (__half*)x1h, n4x);

        int n4w = MM * DIN / 4;
        dim3 g2((n4w + 255) / 256, 2);
        cvt2_fp16<<<g2, 256>>>(W0, (__half*)W0h, n4w, W1, (__half*)W1h, n4w);

        int n4wb = CC * SS * SS * SS / 4;
        int n4wo = OUTN * MM / 4;
        int nmax = n4wb > n4wo ? n4wb : n4wo;
        dim3 g3((nmax + 255) / 256, 2);
        cvt2_fp16<<<g3, 256>>>(Wb, (__half*)Wbh, n4wb, Wout, (__half*)Woh, n4wo);
    }

    // merged input GEMMs (1-product)
    {
        dim3 grid((MM + 127) / 128, BB / 128, 2);
        tc_gemm_in<<<grid, 256, SMEM1>>>(
            (const __half*)x0h, (const __half*)x1h,
            (const __half*)W0h, (const __half*)W1h,
            b0, b1, h0p, (__half*)h1h, MM, DIN);
    }

    // fused bilinear + bias + signed-sqrt + normalize -> fp16 zh
    {
        dim3 grid(BB / 128, CC);
        bilq_kernel<<<grid, 256, BIL_SMEM>>>(
            (const __half*)Wbh, (const __half*)h1h, h0p, bb, (__half*)zh);
    }

    // out = z @ Wout^T + bout (1-product)
    {
        dim3 grid((OUTN + 127) / 128, BB / 128);
        tc_gemm_out<<<grid, 256, SMEM1>>>(
            (const __half*)zh, (const __half*)Woh, bout, out, OUTN, MM);
    }
}

// round 15
// speedup vs baseline: 1.1363x; 1.0129x over previous
#include <cuda_runtime.h>
#include <cuda_fp16.h>
#include <math.h>
#include <stdint.h>

// Problem constants
#define BB    8192
#define DIN   2048
#define MM    1600
#define CC    20
#define SS    80
#define OUTN  3000

// ---------------------------------------------------------------------------
// Scratch (static device globals)
// ---------------------------------------------------------------------------
__device__ float g_h0[(size_t)BB * MM];
__device__ float g_zT[(size_t)MM * BB];

__device__ __half g_x0h[(size_t)BB * DIN];
__device__ __half g_x1h[(size_t)BB * DIN];
__device__ __half g_W0h[(size_t)MM * DIN];
__device__ __half g_W1h[(size_t)MM * DIN];
__device__ __half g_Wouth[(size_t)OUTN * MM];
__device__ __half g_Wbh[(size_t)CC * SS * SS * SS];
__device__ __half g_h1h[(size_t)BB * MM];
__device__ __half g_zh[(size_t)BB * MM];

// ---------------------------------------------------------------------------
// Low-level helpers
// ---------------------------------------------------------------------------
__device__ __forceinline__ uint32_t smem_u32(const void* p) {
    uint32_t a;
    asm("{ .reg .u64 t; cvta.to.shared.u64 t, %1; cvt.u32.u64 %0, t; }"
        : "=r"(a) : "l"(p));
    return a;
}

#define CP16(dst, src) \
    asm volatile("cp.async.cg.shared.global [%0], [%1], 16;" \
                 :: "r"(dst), "l"(src) : "memory")
#define CP16P(dst, src, nbytes) \
    asm volatile("cp.async.cg.shared.global [%0], [%1], 16, %2;" \
                 :: "r"(dst), "l"(src), "r"(nbytes) : "memory")
#define CP_COMMIT() asm volatile("cp.async.commit_group;" ::: "memory")
#define CP_WAIT0()  asm volatile("cp.async.wait_group 0;" ::: "memory")
#define CP_WAIT1()  asm volatile("cp.async.wait_group 1;" ::: "memory")

#define LDX4(r0, r1, r2, r3, addr) \
    asm volatile("ldmatrix.sync.aligned.m8n8.x4.shared.b16 {%0,%1,%2,%3}, [%4];" \
                 : "=r"(r0), "=r"(r1), "=r"(r2), "=r"(r3) : "r"(addr))

#define MMAH(d0, d1, d2, d3, a0, a1, a2, a3, b0, b1) \
    asm volatile("mma.sync.aligned.m16n8k16.row.col.f32.f16.f16.f32 " \
                 "{%0,%1,%2,%3}, {%4,%5,%6,%7}, {%8,%9}, {%0,%1,%2,%3};" \
                 : "+f"(d0), "+f"(d1), "+f"(d2), "+f"(d3) \
                 : "r"(a0), "r"(a1), "r"(a2), "r"(a3), "r"(b0), "r"(b1))

// ---------------------------------------------------------------------------
// fp32 -> fp16 converts (paired, independent sizes per grid.y)
// ---------------------------------------------------------------------------
__global__ __launch_bounds__(256)
void cvt2_fp16(const float* __restrict__ in0, __half* __restrict__ out0, int n4a,
               const float* __restrict__ in1, __half* __restrict__ out1, int n4b)
{
    int i = blockIdx.x * blockDim.x + threadIdx.x;
    const float* in = blockIdx.y ? in1 : in0;
    __half* out = blockIdx.y ? out1 : out0;
    int n4 = blockIdx.y ? n4b : n4a;
    if (i >= n4) return;
    float4 v = ((const float4*)in)[i];
    __half2 a = __halves2half2(__float2half(v.x), __float2half(v.y));
    __half2 b = __halves2half2(__float2half(v.z), __float2half(v.w));
    uint2 o;
    o.x = *(uint32_t*)&a; o.y = *(uint32_t*)&b;
    ((uint2*)out)[i] = o;
}

// ---------------------------------------------------------------------------
// 1-product fp16 NT GEMM core: CTA 128x128xBK64, 3-stage, 2 CTAs/SM,
// 256 threads (8 warps, warp tile 64x32), single sync per K-iter.  [R11 cfg]
// ---------------------------------------------------------------------------
#define BK 64
#define STG1 32768            // A 16K | B 16K
#define SMEM1 (3 * STG1)      // 96K

__device__ __forceinline__ void issue1(
    uint32_t sbase, int stage,
    const __half* __restrict__ A, const __half* __restrict__ B,
    int m0, int n0, int k0, int N, int K, int tid)
{
    uint32_t st = sbase + stage * STG1;
#pragma unroll
    for (int i = 0; i < 4; ++i) {
        int idx = tid + i * 256;
        int r = idx >> 3;
        int c = idx & 7;
        uint32_t dst = (uint32_t)(r * 128 + ((c ^ (r & 7)) << 4));
        CP16(st + dst, (const char*)(A + (size_t)(m0 + r) * K + k0 + c * 8));
        int n = n0 + r;
        int pred = (n < N) ? 16 : 0;
        int ncl = (n < N) ? n : (N - 1);
        CP16P(st + 16384 + dst, (const char*)(B + (size_t)ncl * K + k0 + c * 8), pred);
    }
    CP_COMMIT();
}

__device__ __forceinline__ void gemm1_mainloop(
    uint32_t sb, const __half* A, const __half* B,
    int m0, int n0, int N, int K, int tid, float d[4][4][4])
{
    const int l   = tid & 31;
    const int wid = tid >> 5;
    const int wm  = wid & 1;
    const int wn  = wid >> 1;
    const int niter = K / BK;

    const uint32_t aRow  = (uint32_t)(wm * 64 + (l & 15));
    const uint32_t aXor  = aRow & 7;
    const uint32_t aHalf = (uint32_t)(l >> 4);
    const uint32_t bRow  = (uint32_t)(wn * 32 + (l & 7) + ((l >> 4) << 3));
    const uint32_t bXor  = bRow & 7;
    const uint32_t bHalf = (uint32_t)((l >> 3) & 1);

    issue1(sb, 0, A, B, m0, n0, 0, N, K, tid);
    if (niter > 1) issue1(sb, 1, A, B, m0, n0, BK, N, K, tid);

    for (int it = 0; it < niter; ++it) {
        if (it + 1 < niter) CP_WAIT1(); else CP_WAIT0();
        __syncthreads();
        if (it + 2 < niter)
            issue1(sb, (it + 2) % 3, A, B, m0, n0, (it + 2) * BK, N, K, tid);

        const uint32_t st = sb + (it % 3) * STG1;
        const uint32_t sA = st;
        const uint32_t sB = st + 16384;

#pragma unroll
        for (int kk = 0; kk < 4; ++kk) {
            uint32_t ah[4][4], bh[2][4];
            const uint32_t ach = (((2 * kk + aHalf) ^ aXor) << 4);
            const uint32_t bch = (((2 * kk + bHalf) ^ bXor) << 4);
#pragma unroll
            for (int mg = 0; mg < 4; ++mg) {
                uint32_t off = (aRow + mg * 16) * 128 + ach;
                LDX4(ah[mg][0], ah[mg][1], ah[mg][2], ah[mg][3], sA + off);
            }
#pragma unroll
            for (int bq = 0; bq < 2; ++bq) {
                uint32_t off = (bRow + bq * 16) * 128 + bch;
                LDX4(bh[bq][0], bh[bq][1], bh[bq][2], bh[bq][3], sB + off);
            }
#pragma unroll
            for (int mg = 0; mg < 4; ++mg) {
#pragma unroll
                for (int bq = 0; bq < 2; ++bq) {
#pragma unroll
                    for (int hh = 0; hh < 2; ++hh) {
                        float* dd = d[mg][bq * 2 + hh];
                        MMAH(dd[0], dd[1], dd[2], dd[3],
                             ah[mg][0], ah[mg][1], ah[mg][2], ah[mg][3],
                             bh[bq][2 * hh], bh[bq][2 * hh + 1]);
                    }
                }
            }
        }
    }
}

// Merged input GEMMs: blockIdx.z=0 -> h0 fp32; z=1 -> h1 fp16.
__global__ __launch_bounds__(256, 2)
void tc_gemm_in(const __half* __restrict__ A0, const __half* __restrict__ A1,
                const __half* __restrict__ B0, const __half* __restrict__ B1,
                const float* __restrict__ bias0, const float* __restrict__ bias1,
                float* __restrict__ C0, __half* __restrict__ C1,
                int N, int K)
{
    extern __shared__ __align__(128) char smem[];
    const uint32_t sb = smem_u32(smem);
    const int tid = threadIdx.x;
    const int which = blockIdx.z;
    const int m0 = blockIdx.y * 128;
    const int n0 = blockIdx.x * 128;

    const __half* A   = which ? A1 : A0;
    const __half* B   = which ? B1 : B0;
    const float* bias = which ? bias1 : bias0;

    float d[4][4][4];
#pragma unroll
    for (int mg = 0; mg < 4; ++mg)
#pragma unroll
        for (int ng = 0; ng < 4; ++ng)
#pragma unroll
            for (int e = 0; e < 4; ++e) d[mg][ng][e] = 0.0f;

    gemm1_mainloop(sb, A, B, m0, n0, N, K, tid, d);

    const int l  = tid & 31;
    const int wm = (tid >> 5) & 1;
    const int wn = tid >> 6;
#pragma unroll
    for (int mg = 0; mg < 4; ++mg) {
#pragma unroll
        for (int ng = 0; ng < 4; ++ng) {
            int m = m0 + wm * 64 + mg * 16 + (l >> 2);
            int n = n0 + wn * 32 + ng * 8 + 2 * (l & 3);
            if (n < N) {
                float v0 = d[mg][ng][0] + bias[n];
                float v1 = d[mg][ng][1] + bias[n + 1];
                float v2 = d[mg][ng][2] + bias[n];
                float v3 = d[mg][ng][3] + bias[n + 1];
                if (!which) {
                    *(float2*)&C0[(size_t)m * N + n] = make_float2(v0, v1);
                    *(float2*)&C0[(size_t)(m + 8) * N + n] = make_float2(v2, v3);
                } else {
                    *(__half2*)&C1[(size_t)m * N + n] =
                        __halves2half2(__float2half(v0), __float2half(v1));
                    *(__half2*)&C1[(size_t)(m + 8) * N + n] =
                        __halves2half2(__float2half(v2), __float2half(v3));
                }
            }
        }
    }
}

// Out GEMM: fp32 output
__global__ __launch_bounds__(256, 2)
void tc_gemm_out(const __half* __restrict__ A, const __half* __restrict__ B,
                 const float* __restrict__ bias, float* __restrict__ C,
                 int N, int K)
{
    extern __shared__ __align__(128) char smem[];
    const uint32_t sb = smem_u32(smem);
    const int tid = threadIdx.x;
    const int m0 = blockIdx.y * 128;
    const int n0 = blockIdx.x * 128;

    float d[4][4][4];
#pragma unroll
    for (int mg = 0; mg < 4; ++mg)
#pragma unroll
        for (int ng = 0; ng < 4; ++ng)
#pragma unroll
            for (int e = 0; e < 4; ++e) d[mg][ng][e] = 0.0f;

    gemm1_mainloop(sb, A, B, m0, n0, N, K, tid, d);

    const int l  = tid & 31;
    const int wm = (tid >> 5) & 1;
    const int wn = tid >> 6;
#pragma unroll
    for (int mg = 0; mg < 4; ++mg) {
#pragma unroll
        for (int ng = 0; ng < 4; ++ng) {
            int m = m0 + wm * 64 + mg * 16 + (l >> 2);
            int n = n0 + wn * 32 + ng * 8 + 2 * (l & 3);
            if (n < N) {
                float v0 = d[mg][ng][0] + bias[n];
                float v1 = d[mg][ng][1] + bias[n + 1];
                float v2 = d[mg][ng][2] + bias[n];
                float v3 = d[mg][ng][3] + bias[n + 1];
                *(float2*)&C[(size_t)m * N + n] = make_float2(v0, v1);
                *(float2*)&C[(size_t)(m + 8) * N + n] = make_float2(v2, v3);
            }
        }
    }
}

// ---------------------------------------------------------------------------
// Fused bilinear (fp16 1-product), batch-resident layout [R11] with per-qp
// A-fragment hoist: Wb fragments are identical for both b-tiles of a qp, so
// load the 25 LDX4 once per qp and reuse (mainloop smem traffic -35%).
// CTA = (c, 256-batch block); h0/h1 resident; Wb double-buffered (40 q-pairs).
// ---------------------------------------------------------------------------
#define WB_PITCH 176
#define H1_PITCH 176
#define H0_PITCHB 336
#define H0_PITCHF 84
#define WB_STAGE 28160
#define SH1 56320
#define SH0 101376
#define BIL_SMEM 187392

__device__ __forceinline__ void issue_wb(
    uint32_t sb, int buf, const __half* __restrict__ Wbh,
    int c, int qp, int tid)
{
    const size_t wb_base = (size_t)c * (SS * SS * SS) + (size_t)(qp * 2) * (SS * SS);
    uint32_t base = sb + buf * WB_STAGE;
#pragma unroll
    for (int i = 0; i < 7; ++i) {
        int idx = tid + i * 256;
        if (idx < 1600) {
            int row = idx / 10, ch = idx % 10;
            size_t src = wb_base + (size_t)(row / 80) * (SS * SS)
                       + (size_t)(row % 80) * SS + ch * 8;
            CP16(base + row * WB_PITCH + ch * 16, (const char*)(Wbh + src));
        }
    }
    CP_COMMIT();
}

__global__ __launch_bounds__(256, 1)
void bilq_kernel(const __half* __restrict__ Wbh,
                 const __half* __restrict__ h1h,
                 const float* __restrict__ h0g,
                 float* __restrict__ zT)
{
    extern __shared__ __align__(128) char smem[];
    const uint32_t sb = smem_u32(smem);
    const int tid = threadIdx.x;
    const int l   = tid & 31;
    const int wid = tid >> 5;
    const int wm  = wid >> 2;
    const int wn  = wid & 3;
    const int c     = blockIdx.y;
    const int bbase = blockIdx.x * 256;

#pragma unroll
    for (int i = 0; i < 10; ++i) {
        int idx = tid + i * 256;
        int r = idx / 10, ch = idx % 10;
        size_t src = (size_t)(bbase + r) * MM + c * SS + ch * 8;
        CP16(sb + SH1 + r * H1_PITCH + ch * 16, (const char*)(h1h + src));
    }
#pragma unroll
    for (int i = 0; i < 20; ++i) {
        int idx = tid + i * 256;
        int r = idx / 20, ch = idx % 20;
        size_t src = (size_t)(bbase + r) * MM + c * SS + ch * 4;
        CP16(sb + SH0 + r * H0_PITCHB + ch * 16, (const char*)(h0g + src));
    }
    issue_wb(sb, 0, Wbh, c, 0, tid);
    issue_wb(sb, 1, Wbh, c, 1, tid);

    const uint32_t aRowOff = (uint32_t)(wm * 80 + (l & 15)) * WB_PITCH;
    const uint32_t aHalf   = (uint32_t)(l >> 4);
    const uint32_t bRowOff = (uint32_t)((l & 7) + ((l >> 4) << 3)) * H1_PITCH;
    const uint32_t bHalf   = (uint32_t)((l >> 3) & 1);

    for (int qp = 0; qp < 40; ++qp) {
        if (qp + 1 < 40) CP_WAIT1(); else CP_WAIT0();
        __syncthreads();
        const uint32_t sA = sb + (qp & 1) * WB_STAGE;

        // --- per-qp A-fragment hoist (reused by both b-tiles) ---
        uint32_t ahq[5][5][4];
#pragma unroll
        for (int kk = 0; kk < 5; ++kk) {
            const uint32_t aco = ((2 * kk + aHalf) << 4);
#pragma unroll
            for (int mt = 0; mt < 5; ++mt) {
                uint32_t off = aRowOff + mt * 16 * WB_PITCH + aco;
                LDX4(ahq[kk][mt][0], ahq[kk][mt][1],
                     ahq[kk][mt][2], ahq[kk][mt][3], sA + off);
            }
        }

#pragma unroll
        for (int bt = 0; bt < 2; ++bt) {
            const uint32_t sB = sb + SH1 + (uint32_t)(bt * 128) * H1_PITCH;
            const float* h0s = (const float*)(smem + SH0 + bt * 128 * H0_PITCHB);
            const int b0 = bbase + bt * 128;

            float d[5][4][4];
#pragma unroll
            for (int mt = 0; mt < 5; ++mt)
#pragma unroll
                for (int nt = 0; nt < 4; ++nt)
#pragma unroll
                    for (int e = 0; e < 4; ++e) d[mt][nt][e] = 0.0f;

#pragma unroll
            for (int kk = 0; kk < 5; ++kk) {
                uint32_t bh[2][4];
                const uint32_t bco = ((2 * kk + bHalf) << 4);
#pragma unroll
                for (int pr = 0; pr < 2; ++pr) {
                    uint32_t off = (uint32_t)(wn * 32 + pr * 16) * H1_PITCH
                                 + bRowOff + bco;
                    LDX4(bh[pr][0], bh[pr][1], bh[pr][2], bh[pr][3], sB + off);
                }
#pragma unroll
                for (int mt = 0; mt < 5; ++mt) {
#pragma unroll
                    for (int pr = 0; pr < 2; ++pr) {
#pragma unroll
                        for (int hh = 0; hh < 2; ++hh) {
                            int nt = pr * 2 + hh;
                            float* dd = d[mt][nt];
                            MMAH(dd[0], dd[1], dd[2], dd[3],
                                 ahq[kk][mt][0], ahq[kk][mt][1],
                                 ahq[kk][mt][2], ahq[kk][mt][3],
                                 bh[pr][2 * hh], bh[pr][2 * hh + 1]);
                        }
                    }
                }
            }

            float p8[8];
#pragma unroll
            for (int i = 0; i < 8; ++i) p8[i] = 0.0f;
#pragma unroll
            for (int mt = 0; mt < 5; ++mt) {
#pragma unroll
                for (int e = 0; e < 4; ++e) {
                    int s = mt * 16 + (l >> 2) + 8 * (e >> 1);
#pragma unroll
                    for (int nt = 0; nt < 4; ++nt) {
                        int bl_ = wn * 32 + nt * 8 + 2 * (l & 3) + (e & 1);
                        p8[nt * 2 + (e & 1)] += d[mt][nt][e] * h0s[bl_ * H0_PITCHF + s];
                    }
                }
            }
#pragma unroll
            for (int pi = 0; pi < 8; ++pi) {
                float v = p8[pi];
                v += __shfl_xor_sync(0xffffffffu, v, 4);
                v += __shfl_xor_sync(0xffffffffu, v, 8);
                v += __shfl_xor_sync(0xffffffffu, v, 16);
                p8[pi] = v;
            }
            if (l < 4) {
                int feat = c * SS + qp * 2 + wm;
                float* dst = zT + (size_t)feat * BB + b0 + wn * 32 + 2 * l;
#pragma unroll
                for (int nt = 0; nt < 4; ++nt)
                    *(float2*)(dst + nt * 8) = make_float2(p8[nt * 2], p8[nt * 2 + 1]);
            }
        }

        __syncthreads();
        if (qp + 2 < 40)
            issue_wb(sb, qp & 1, Wbh, c, qp + 2, tid);
    }
}

// ---------------------------------------------------------------------------
// norm: z = signed_sqrt(zT + bb); per-chunk L2 normalize; emit fp16.
// ---------------------------------------------------------------------------
__global__ __launch_bounds__(256)
void norm_kernel(const float* __restrict__ zT, const float* __restrict__ bbv,
                 __half* __restrict__ zh)
{
    __shared__ float zs[80 * 129];
    __shared__ float bbs[80];
    __shared__ float scl[128];
    const int tid = threadIdx.x;
    const int c = blockIdx.y;
    const int b0 = blockIdx.x * 128;

    if (tid < 80) bbs[tid] = bbv[c * SS + tid];
#pragma unroll
    for (int i = 0; i < 40; ++i) {
        int idx = tid + i * 256;
        int q = idx >> 7, col = idx & 127;
        zs[q * 129 + col] = zT[(size_t)(c * SS + q) * BB + b0 + col];
    }
    __syncthreads();
    if (tid < 128) {
        float s = 0.0f;
#pragma unroll 4
        for (int q = 0; q < 80; ++q) s += fabsf(zs[q * 129 + tid] + bbs[q]);
        scl[tid] = 1.0f / fmaxf(sqrtf(s), 1e-12f);
    }
    __syncthreads();
#pragma unroll
    for (int i = 0; i < 40; ++i) {
        int idx = tid + i * 256;
        int b = idx / 80, q = idx % 80;
        float v = zs[q * 129 + b] + bbs[q];
        float sv = copysignf(sqrtf(fabsf(v)), v) * scl[b];
        zh[(size_t)(b0 + b) * MM + c * SS + q] = __float2half(sv);
    }
}

// ---------------------------------------------------------------------------
// launch
// ---------------------------------------------------------------------------
extern "C" void kernel_launch(void* const* d_in, const int* in_sizes, int n_in,
                              void* d_out, int out_size)
{
    (void)in_sizes; (void)n_in; (void)out_size;
    const float* x0   = (const float*)d_in[0];
    const float* x1   = (const float*)d_in[1];
    const float* W0   = (const float*)d_in[2];
    const float* b0   = (const float*)d_in[3];
    const float* W1   = (const float*)d_in[4];
    const float* b1   = (const float*)d_in[5];
    const float* Wb   = (const float*)d_in[6];
    const float* bb   = (const float*)d_in[7];
    const float* Wout = (const float*)d_in[8];
    const float* bout = (const float*)d_in[9];
    float* out = (float*)d_out;

    float *h0p, *zTp;
    cudaGetSymbolAddress((void**)&h0p, g_h0);
    cudaGetSymbolAddress((void**)&zTp, g_zT);
    void *x0h, *x1h, *W0h, *W1h, *Woh, *Wbh, *h1h, *zh;
    cudaGetSymbolAddress(&x0h, g_x0h);  cudaGetSymbolAddress(&x1h, g_x1h);
    cudaGetSymbolAddress(&W0h, g_W0h);  cudaGetSymbolAddress(&W1h, g_W1h);
    cudaGetSymbolAddress(&Woh, g_Wouth);
    cudaGetSymbolAddress(&Wbh, g_Wbh);
    cudaGetSymbolAddress(&h1h, g_h1h);
    cudaGetSymbolAddress(&zh, g_zh);

    cudaFuncSetAttribute(tc_gemm_in, cudaFuncAttributeMaxDynamicSharedMemorySize, SMEM1);
    cudaFuncSetAttribute(tc_gemm_out, cudaFuncAttributeMaxDynamicSharedMemorySize, SMEM1);
    cudaFuncSetAttribute(bilq_kernel, cudaFuncAttributeMaxDynamicSharedMemorySize, BIL_SMEM);

    // converts (3 launches)
    {
        int n4x = BB * DIN / 4;
        dim3 g((n4x + 255) / 256, 2);
        cvt2_fp16<<<g, 256>>>(x0, (__half*)x0h, n4x, x1, (__half*)x1h, n4x);

        int n4w = MM * DIN / 4;
        dim3 g2((n4w + 255) / 256, 2);
        cvt2_fp16<<<g2, 256>>>(W0, (__half*)W0h, n4w, W1, (__half*)W1h, n4w);

        int n4wb = CC * SS * SS * SS / 4;
        int n4wo = OUTN * MM / 4;
        int nmax = n4wb > n4wo ? n4wb : n4wo;
        dim3 g3((nmax + 255) / 256, 2);
        cvt2_fp16<<<g3, 256>>>(Wb, (__half*)Wbh, n4wb, Wout, (__half*)Woh, n4wo);
    }

    // merged input GEMMs (1-product)
    {
        dim3 grid((MM + 127) / 128, BB / 128, 2);
        tc_gemm_in<<<grid, 256, SMEM1>>>(
            (const __half*)x0h, (const __half*)x1h,
            (const __half*)W0h, (const __half*)W1h,
            b0, b1, h0p, (__half*)h1h, MM, DIN);
    }

    // fused bilinear -> zT (batch-resident, Wb streamed, A-hoisted)
    {
        dim3 grid(BB / 256, CC);
        bilq_kernel<<<grid, 256, BIL_SMEM>>>(
            (const __half*)Wbh, (const __half*)h1h, h0p, zTp);
    }

    // bias + signed sqrt + normalize -> fp16 z
    {
        dim3 grid(BB / 128, CC);
        norm_kernel<<<grid, 256>>>(zTp, bb, (__half*)zh);
    }

    // out = z @ Wout^T + bout (1-product)
    {
        dim3 grid((OUTN + 127) / 128, BB / 128);
        tc_gemm_out<<<grid, 256, SMEM1>>>(
            (const __half*)zh, (const __half*)Woh, bout, out, OUTN, MM);
    }
}

// round 16
// speedup vs baseline: 1.1743x; 1.0334x over previous
#include <cuda_runtime.h>
#include <cuda_fp16.h>
#include <math.h>
#include <stdint.h>

// Problem constants
#define BB    8192
#define DIN   2048
#define MM    1600
#define CC    20
#define SS    80
#define OUTN  3000

// ---------------------------------------------------------------------------
// Scratch (static device globals)
// ---------------------------------------------------------------------------
__device__ float g_h0[(size_t)BB * MM];
__device__ float g_zT[(size_t)MM * BB];

__device__ __half g_x0h[(size_t)BB * DIN];
__device__ __half g_x1h[(size_t)BB * DIN];
__device__ __half g_W0h[(size_t)MM * DIN];
__device__ __half g_W1h[(size_t)MM * DIN];
__device__ __half g_Wouth[(size_t)OUTN * MM];
__device__ __half g_Wbh[(size_t)CC * SS * SS * SS];
__device__ __half g_h1h[(size_t)BB * MM];
__device__ __half g_zh[(size_t)BB * MM];

// ---------------------------------------------------------------------------
// Low-level helpers
// ---------------------------------------------------------------------------
__device__ __forceinline__ uint32_t smem_u32(const void* p) {
    uint32_t a;
    asm("{ .reg .u64 t; cvta.to.shared.u64 t, %1; cvt.u32.u64 %0, t; }"
        : "=r"(a) : "l"(p));
    return a;
}

#define CP16(dst, src) \
    asm volatile("cp.async.cg.shared.global [%0], [%1], 16;" \
                 :: "r"(dst), "l"(src) : "memory")
#define CP16P(dst, src, nbytes) \
    asm volatile("cp.async.cg.shared.global [%0], [%1], 16, %2;" \
                 :: "r"(dst), "l"(src), "r"(nbytes) : "memory")
#define CP_COMMIT() asm volatile("cp.async.commit_group;" ::: "memory")
#define CP_WAIT0()  asm volatile("cp.async.wait_group 0;" ::: "memory")
#define CP_WAIT1()  asm volatile("cp.async.wait_group 1;" ::: "memory")

#define LDX4(r0, r1, r2, r3, addr) \
    asm volatile("ldmatrix.sync.aligned.m8n8.x4.shared.b16 {%0,%1,%2,%3}, [%4];" \
                 : "=r"(r0), "=r"(r1), "=r"(r2), "=r"(r3) : "r"(addr))

#define MMAH(d0, d1, d2, d3, a0, a1, a2, a3, b0, b1) \
    asm volatile("mma.sync.aligned.m16n8k16.row.col.f32.f16.f16.f32 " \
                 "{%0,%1,%2,%3}, {%4,%5,%6,%7}, {%8,%9}, {%0,%1,%2,%3};" \
                 : "+f"(d0), "+f"(d1), "+f"(d2), "+f"(d3) \
                 : "r"(a0), "r"(a1), "r"(a2), "r"(a3), "r"(b0), "r"(b1))

// ---------------------------------------------------------------------------
// fp32 -> fp16 converts (paired, independent sizes per grid.y)
// ---------------------------------------------------------------------------
__global__ __launch_bounds__(256)
void cvt2_fp16(const float* __restrict__ in0, __half* __restrict__ out0, int n4a,
               const float* __restrict__ in1, __half* __restrict__ out1, int n4b)
{
    int i = blockIdx.x * blockDim.x + threadIdx.x;
    const float* in = blockIdx.y ? in1 : in0;
    __half* out = blockIdx.y ? out1 : out0;
    int n4 = blockIdx.y ? n4b : n4a;
    if (i >= n4) return;
    float4 v = ((const float4*)in)[i];
    __half2 a = __halves2half2(__float2half(v.x), __float2half(v.y));
    __half2 b = __halves2half2(__float2half(v.z), __float2half(v.w));
    uint2 o;
    o.x = *(uint32_t*)&a; o.y = *(uint32_t*)&b;
    ((uint2*)out)[i] = o;
}

// ---------------------------------------------------------------------------
// 1-product fp16 NT GEMM core: CTA 128x128xBK64, 3-stage, 2 CTAs/SM,
// 256 threads (8 warps, warp tile 64x32), single sync per K-iter.  [R11 cfg]
// ---------------------------------------------------------------------------
#define BK 64
#define STG1 32768            // A 16K | B 16K
#define SMEM1 (3 * STG1)      // 96K

__device__ __forceinline__ void issue1(
    uint32_t sbase, int stage,
    const __half* __restrict__ A, const __half* __restrict__ B,
    int m0, int n0, int k0, int N, int K, int tid)
{
    uint32_t st = sbase + stage * STG1;
#pragma unroll
    for (int i = 0; i < 4; ++i) {
        int idx = tid + i * 256;
        int r = idx >> 3;
        int c = idx & 7;
        uint32_t dst = (uint32_t)(r * 128 + ((c ^ (r & 7)) << 4));
        CP16(st + dst, (const char*)(A + (size_t)(m0 + r) * K + k0 + c * 8));
        int n = n0 + r;
        int pred = (n < N) ? 16 : 0;
        int ncl = (n < N) ? n : (N - 1);
        CP16P(st + 16384 + dst, (const char*)(B + (size_t)ncl * K + k0 + c * 8), pred);
    }
    CP_COMMIT();
}

__device__ __forceinline__ void gemm1_mainloop(
    uint32_t sb, const __half* A, const __half* B,
    int m0, int n0, int N, int K, int tid, float d[4][4][4])
{
    const int l   = tid & 31;
    const int wid = tid >> 5;
    const int wm  = wid & 1;
    const int wn  = wid >> 1;
    const int niter = K / BK;

    const uint32_t aRow  = (uint32_t)(wm * 64 + (l & 15));
    const uint32_t aXor  = aRow & 7;
    const uint32_t aHalf = (uint32_t)(l >> 4);
    const uint32_t bRow  = (uint32_t)(wn * 32 + (l & 7) + ((l >> 4) << 3));
    const uint32_t bXor  = bRow & 7;
    const uint32_t bHalf = (uint32_t)((l >> 3) & 1);

    issue1(sb, 0, A, B, m0, n0, 0, N, K, tid);
    if (niter > 1) issue1(sb, 1, A, B, m0, n0, BK, N, K, tid);

    for (int it = 0; it < niter; ++it) {
        if (it + 1 < niter) CP_WAIT1(); else CP_WAIT0();
        __syncthreads();
        if (it + 2 < niter)
            issue1(sb, (it + 2) % 3, A, B, m0, n0, (it + 2) * BK, N, K, tid);

        const uint32_t st = sb + (it % 3) * STG1;
        const uint32_t sA = st;
        const uint32_t sB = st + 16384;

#pragma unroll
        for (int kk = 0; kk < 4; ++kk) {
            uint32_t ah[4][4], bh[2][4];
            const uint32_t ach = (((2 * kk + aHalf) ^ aXor) << 4);
            const uint32_t bch = (((2 * kk + bHalf) ^ bXor) << 4);
#pragma unroll
            for (int mg = 0; mg < 4; ++mg) {
                uint32_t off = (aRow + mg * 16) * 128 + ach;
                LDX4(ah[mg][0], ah[mg][1], ah[mg][2], ah[mg][3], sA + off);
            }
#pragma unroll
            for (int bq = 0; bq < 2; ++bq) {
                uint32_t off = (bRow + bq * 16) * 128 + bch;
                LDX4(bh[bq][0], bh[bq][1], bh[bq][2], bh[bq][3], sB + off);
            }
#pragma unroll
            for (int mg = 0; mg < 4; ++mg) {
#pragma unroll
                for (int bq = 0; bq < 2; ++bq) {
#pragma unroll
                    for (int hh = 0; hh < 2; ++hh) {
                        float* dd = d[mg][bq * 2 + hh];
                        MMAH(dd[0], dd[1], dd[2], dd[3],
                             ah[mg][0], ah[mg][1], ah[mg][2], ah[mg][3],
                             bh[bq][2 * hh], bh[bq][2 * hh + 1]);
                    }
                }
            }
        }
    }
}

// Merged input GEMMs: blockIdx.z=0 -> h0 fp32; z=1 -> h1 fp16.
__global__ __launch_bounds__(256, 2)
void tc_gemm_in(const __half* __restrict__ A0, const __half* __restrict__ A1,
                const __half* __restrict__ B0, const __half* __restrict__ B1,
                const float* __restrict__ bias0, const float* __restrict__ bias1,
                float* __restrict__ C0, __half* __restrict__ C1,
                int N, int K)
{
    extern __shared__ __align__(128) char smem[];
    const uint32_t sb = smem_u32(smem);
    const int tid = threadIdx.x;
    const int which = blockIdx.z;
    const int m0 = blockIdx.y * 128;
    const int n0 = blockIdx.x * 128;

    const __half* A   = which ? A1 : A0;
    const __half* B   = which ? B1 : B0;
    const float* bias = which ? bias1 : bias0;

    float d[4][4][4];
#pragma unroll
    for (int mg = 0; mg < 4; ++mg)
#pragma unroll
        for (int ng = 0; ng < 4; ++ng)
#pragma unroll
            for (int e = 0; e < 4; ++e) d[mg][ng][e] = 0.0f;

    gemm1_mainloop(sb, A, B, m0, n0, N, K, tid, d);

    const int l  = tid & 31;
    const int wm = (tid >> 5) & 1;
    const int wn = tid >> 6;
#pragma unroll
    for (int mg = 0; mg < 4; ++mg) {
#pragma unroll
        for (int ng = 0; ng < 4; ++ng) {
            int m = m0 + wm * 64 + mg * 16 + (l >> 2);
            int n = n0 + wn * 32 + ng * 8 + 2 * (l & 3);
            if (n < N) {
                float v0 = d[mg][ng][0] + bias[n];
                float v1 = d[mg][ng][1] + bias[n + 1];
                float v2 = d[mg][ng][2] + bias[n];
                float v3 = d[mg][ng][3] + bias[n + 1];
                if (!which) {
                    *(float2*)&C0[(size_t)m * N + n] = make_float2(v0, v1);
                    *(float2*)&C0[(size_t)(m + 8) * N + n] = make_float2(v2, v3);
                } else {
                    *(__half2*)&C1[(size_t)m * N + n] =
                        __halves2half2(__float2half(v0), __float2half(v1));
                    *(__half2*)&C1[(size_t)(m + 8) * N + n] =
                        __halves2half2(__float2half(v2), __float2half(v3));
                }
            }
        }
    }
}

// Out GEMM: fp32 output
__global__ __launch_bounds__(256, 2)
void tc_gemm_out(const __half* __restrict__ A, const __half* __restrict__ B,
                 const float* __restrict__ bias, float* __restrict__ C,
                 int N, int K)
{
    extern __shared__ __align__(128) char smem[];
    const uint32_t sb = smem_u32(smem);
    const int tid = threadIdx.x;
    const int m0 = blockIdx.y * 128;
    const int n0 = blockIdx.x * 128;

    float d[4][4][4];
#pragma unroll
    for (int mg = 0; mg < 4; ++mg)
#pragma unroll
        for (int ng = 0; ng < 4; ++ng)
#pragma unroll
            for (int e = 0; e < 4; ++e) d[mg][ng][e] = 0.0f;

    gemm1_mainloop(sb, A, B, m0, n0, N, K, tid, d);

    const int l  = tid & 31;
    const int wm = (tid >> 5) & 1;
    const int wn = tid >> 6;
#pragma unroll
    for (int mg = 0; mg < 4; ++mg) {
#pragma unroll
        for (int ng = 0; ng < 4; ++ng) {
            int m = m0 + wm * 64 + mg * 16 + (l >> 2);
            int n = n0 + wn * 32 + ng * 8 + 2 * (l & 3);
            if (n < N) {
                float v0 = d[mg][ng][0] + bias[n];
                float v1 = d[mg][ng][1] + bias[n + 1];
                float v2 = d[mg][ng][2] + bias[n];
                float v3 = d[mg][ng][3] + bias[n + 1];
                *(float2*)&C[(size_t)m * N + n] = make_float2(v0, v1);
                *(float2*)&C[(size_t)(m + 8) * N + n] = make_float2(v2, v3);
            }
        }
    }
}

// ---------------------------------------------------------------------------
// Fused bilinear (fp16 1-product), 2 CTAs/SM layout:
// CTA = (c, 128-batch block); 8 warps each own 16 b (warp tile 80s x 16b,
// d[5][2][4] = 40 regs). The 2 q's of a q-pair are processed sequentially.
// h0/h1 resident; Wb single-buffered (next qp load issued after trailing
// sync, hidden by the co-resident CTA). smem = 93.7 KB -> 2 CTAs/SM.
//   zT[c*80+q][b] = sum_s h0[b,s] * (Wb[c,q,s,:] . h1[b,:])
// ---------------------------------------------------------------------------
#define WB_PITCH 176
#define H1_PITCH 176
#define H0_PITCHB 336
#define H0_PITCHF 84
#define SH1B 28160           // after Wb buffer (160*176)
#define SH0B 50688           // SH1B + 128*176
#define BIL_SMEM 93696       // SH0B + 128*336

__device__ __forceinline__ void issue_wb(
    uint32_t sb, const __half* __restrict__ Wbh, int c, int qp, int tid)
{
    const size_t wb_base = (size_t)c * (SS * SS * SS) + (size_t)(qp * 2) * (SS * SS);
#pragma unroll
    for (int i = 0; i < 7; ++i) {
        int idx = tid + i * 256;
        if (idx < 1600) {
            int row = idx / 10, ch = idx % 10;
            size_t src = wb_base + (size_t)(row / 80) * (SS * SS)
                       + (size_t)(row % 80) * SS + ch * 8;
            CP16(sb + row * WB_PITCH + ch * 16, (const char*)(Wbh + src));
        }
    }
    CP_COMMIT();
}

__global__ __launch_bounds__(256, 2)
void bilq_kernel(const __half* __restrict__ Wbh,
                 const __half* __restrict__ h1h,
                 const float* __restrict__ h0g,
                 float* __restrict__ zT)
{
    extern __shared__ __align__(128) char smem[];
    const uint32_t sb = smem_u32(smem);
    const int tid = threadIdx.x;
    const int l   = tid & 31;
    const int wn  = tid >> 5;      // 8 warps x 16 b
    const int c   = blockIdx.y;
    const int b0  = blockIdx.x * 128;

    // ---- prologue: h1, h0 (resident), Wb(qp=0); one cp.async group ----
#pragma unroll
    for (int i = 0; i < 5; ++i) {
        int idx = tid + i * 256;      // 1280 = 128 rows x 10 chunks
        int r = idx / 10, ch = idx % 10;
        size_t src = (size_t)(b0 + r) * MM + c * SS + ch * 8;
        CP16(sb + SH1B + r * H1_PITCH + ch * 16, (const char*)(h1h + src));
    }
#pragma unroll
    for (int i = 0; i < 10; ++i) {
        int idx = tid + i * 256;      // 2560 = 128 rows x 20 chunks
        int r = idx / 20, ch = idx % 20;
        size_t src = (size_t)(b0 + r) * MM + c * SS + ch * 4;
        CP16(sb + SH0B + r * H0_PITCHB + ch * 16, (const char*)(h0g + src));
    }
    issue_wb(sb, Wbh, c, 0, tid);

    const uint32_t aHalf = (uint32_t)(l >> 4);
    const uint32_t bRow  = (uint32_t)(wn * 16 + (l & 7) + ((l >> 4) << 3));
    const uint32_t bHalf = (uint32_t)((l >> 3) & 1);
    const uint32_t sB = sb + SH1B;
    const float* h0s = (const float*)(smem + SH0B);

    for (int qp = 0; qp < 40; ++qp) {
        CP_WAIT0();
        __syncthreads();

#pragma unroll
        for (int ql = 0; ql < 2; ++ql) {
            const uint32_t aRowOff = (uint32_t)(ql * 80 + (l & 15)) * WB_PITCH;

            float d[5][2][4];
#pragma unroll
            for (int mt = 0; mt < 5; ++mt)
#pragma unroll
                for (int nt = 0; nt < 2; ++nt)
#pragma unroll
                    for (int e = 0; e < 4; ++e) d[mt][nt][e] = 0.0f;

#pragma unroll
            for (int kk = 0; kk < 5; ++kk) {
                uint32_t ah[5][4], bh[4];
                const uint32_t aco = ((2 * kk + aHalf) << 4);
                const uint32_t bco = ((2 * kk + bHalf) << 4);
#pragma unroll
                for (int mt = 0; mt < 5; ++mt) {
                    uint32_t off = aRowOff + mt * 16 * WB_PITCH + aco;
                    LDX4(ah[mt][0], ah[mt][1], ah[mt][2], ah[mt][3], sb + off);
                }
                LDX4(bh[0], bh[1], bh[2], bh[3],
                     sB + bRow * H1_PITCH + bco);
#pragma unroll
                for (int mt = 0; mt < 5; ++mt) {
#pragma unroll
                    for (int hh = 0; hh < 2; ++hh) {
                        float* dd = d[mt][hh];
                        MMAH(dd[0], dd[1], dd[2], dd[3],
                             ah[mt][0], ah[mt][1], ah[mt][2], ah[mt][3],
                             bh[2 * hh], bh[2 * hh + 1]);
                    }
                }
            }

            // fused fp32 s-contraction epilogue for q = qp*2+ql
            float p4[4];
#pragma unroll
            for (int i = 0; i < 4; ++i) p4[i] = 0.0f;
#pragma unroll
            for (int mt = 0; mt < 5; ++mt) {
#pragma unroll
                for (int e = 0; e < 4; ++e) {
                    int s = mt * 16 + (l >> 2) + 8 * (e >> 1);
#pragma unroll
                    for (int nt = 0; nt < 2; ++nt) {
                        int bl_ = wn * 16 + nt * 8 + 2 * (l & 3) + (e & 1);
                        p4[nt * 2 + (e & 1)] += d[mt][nt][e] * h0s[bl_ * H0_PITCHF + s];
                    }
                }
            }
#pragma unroll
            for (int pi = 0; pi < 4; ++pi) {
                float v = p4[pi];
                v += __shfl_xor_sync(0xffffffffu, v, 4);
                v += __shfl_xor_sync(0xffffffffu, v, 8);
                v += __shfl_xor_sync(0xffffffffu, v, 16);
                p4[pi] = v;
            }
            if (l < 4) {
                int feat = c * SS + qp * 2 + ql;
                float* dst = zT + (size_t)feat * BB + b0 + wn * 16 + 2 * l;
                *(float2*)dst = make_float2(p4[0], p4[1]);
                *(float2*)(dst + 8) = make_float2(p4[2], p4[3]);
            }
        }

        __syncthreads();      // all warps done reading Wb buffer
        if (qp + 1 < 40)
            issue_wb(sb, Wbh, c, qp + 1, tid);
    }
}

// ---------------------------------------------------------------------------
// norm: z = signed_sqrt(zT + bb); per-chunk L2 normalize; emit fp16.
// ---------------------------------------------------------------------------
__global__ __launch_bounds__(256)
void norm_kernel(const float* __restrict__ zT, const float* __restrict__ bbv,
                 __half* __restrict__ zh)
{
    __shared__ float zs[80 * 129];
    __shared__ float bbs[80];
    __shared__ float scl[128];
    const int tid = threadIdx.x;
    const int c = blockIdx.y;
    const int b0 = blockIdx.x * 128;

    if (tid < 80) bbs[tid] = bbv[c * SS + tid];
#pragma unroll
    for (int i = 0; i < 40; ++i) {
        int idx = tid + i * 256;
        int q = idx >> 7, col = idx & 127;
        zs[q * 129 + col] = zT[(size_t)(c * SS + q) * BB + b0 + col];
    }
    __syncthreads();
    if (tid < 128) {
        float s = 0.0f;
#pragma unroll 4
        for (int q = 0; q < 80; ++q) s += fabsf(zs[q * 129 + tid] + bbs[q]);
        scl[tid] = 1.0f / fmaxf(sqrtf(s), 1e-12f);
    }
    __syncthreads();
#pragma unroll
    for (int i = 0; i < 40; ++i) {
        int idx = tid + i * 256;
        int b = idx / 80, q = idx % 80;
        float v = zs[q * 129 + b] + bbs[q];
        float sv = copysignf(sqrtf(fabsf(v)), v) * scl[b];
        zh[(size_t)(b0 + b) * MM + c * SS + q] = __float2half(sv);
    }
}

// ---------------------------------------------------------------------------
// launch
// ---------------------------------------------------------------------------
extern "C" void kernel_launch(void* const* d_in, const int* in_sizes, int n_in,
                              void* d_out, int out_size)
{
    (void)in_sizes; (void)n_in; (void)out_size;
    const float* x0   = (const float*)d_in[0];
    const float* x1   = (const float*)d_in[1];
    const float* W0   = (const float*)d_in[2];
    const float* b0   = (const float*)d_in[3];
    const float* W1   = (const float*)d_in[4];
    const float* b1   = (const float*)d_in[5];
    const float* Wb   = (const float*)d_in[6];
    const float* bb   = (const float*)d_in[7];
    const float* Wout = (const float*)d_in[8];
    const float* bout = (const float*)d_in[9];
    float* out = (float*)d_out;

    float *h0p, *zTp;
    cudaGetSymbolAddress((void**)&h0p, g_h0);
    cudaGetSymbolAddress((void**)&zTp, g_zT);
    void *x0h, *x1h, *W0h, *W1h, *Woh, *Wbh, *h1h, *zh;
    cudaGetSymbolAddress(&x0h, g_x0h);  cudaGetSymbolAddress(&x1h, g_x1h);
    cudaGetSymbolAddress(&W0h, g_W0h);  cudaGetSymbolAddress(&W1h, g_W1h);
    cudaGetSymbolAddress(&Woh, g_Wouth);
    cudaGetSymbolAddress(&Wbh, g_Wbh);
    cudaGetSymbolAddress(&h1h, g_h1h);
    cudaGetSymbolAddress(&zh, g_zh);

    cudaFuncSetAttribute(tc_gemm_in, cudaFuncAttributeMaxDynamicSharedMemorySize, SMEM1);
    cudaFuncSetAttribute(tc_gemm_out, cudaFuncAttributeMaxDynamicSharedMemorySize, SMEM1);
    cudaFuncSetAttribute(bilq_kernel, cudaFuncAttributeMaxDynamicSharedMemorySize, BIL_SMEM);

    // converts (3 launches)
    {
        int n4x = BB * DIN / 4;
        dim3 g((n4x + 255) / 256, 2);
        cvt2_fp16<<<g, 256>>>(x0, (__half*)x0h, n4x, x1, (__half*)x1h, n4x);

        int n4w = MM * DIN / 4;
        dim3 g2((n4w + 255) / 256, 2);
        cvt2_fp16<<<g2, 256>>>(W0, (__half*)W0h, n4w, W1, (__half*)W1h, n4w);

        int n4wb = CC * SS * SS * SS / 4;
        int n4wo = OUTN * MM / 4;
        int nmax = n4wb > n4wo ? n4wb : n4wo;
        dim3 g3((nmax + 255) / 256, 2);
        cvt2_fp16<<<g3, 256>>>(Wb, (__half*)Wbh, n4wb, Wout, (__half*)Woh, n4wo);
    }

    // merged input GEMMs (1-product)
    {
        dim3 grid((MM + 127) / 128, BB / 128, 2);
        tc_gemm_in<<<grid, 256, SMEM1>>>(
            (const __half*)x0h, (const __half*)x1h,
            (const __half*)W0h, (const __half*)W1h,
            b0, b1, h0p, (__half*)h1h, MM, DIN);
    }

    // fused bilinear -> zT (128-b CTAs, 2 CTAs/SM)
    {
        dim3 grid(BB / 128, CC);
        bilq_kernel<<<grid, 256, BIL_SMEM>>>(
            (const __half*)Wbh, (const __half*)h1h, h0p, zTp);
    }

    // bias + signed sqrt + normalize -> fp16 z
    {
        dim3 grid(BB / 128, CC);
        norm_kernel<<<grid, 256>>>(zTp, bb, (__half*)zh);
    }

    // out = z @ Wout^T + bout (1-product)
    {
        dim3 grid((OUTN + 127) / 128, BB / 128);
        tc_gemm_out<<<grid, 256, SMEM1>>>(
            (const __half*)zh, (const __half*)Woh, bout, out, OUTN, MM);
    }
}

// round 17
// speedup vs baseline: 1.1802x; 1.0050x over previous
#include <cuda_runtime.h>
#include <cuda_fp16.h>
#include <math.h>
#include <stdint.h>

// Problem constants
#define BB    8192
#define DIN   2048
#define MM    1600
#define CC    20
#define SS    80
#define OUTN  3000

// ---------------------------------------------------------------------------
// Scratch (static device globals)
// ---------------------------------------------------------------------------
__device__ float g_h0[(size_t)BB * MM];
__device__ __half g_zT16[(size_t)MM * BB];   // raw z (pre-bias-norm), [feat][b]

__device__ __half g_x0h[(size_t)BB * DIN];
__device__ __half g_x1h[(size_t)BB * DIN];
__device__ __half g_W0h[(size_t)MM * DIN];
__device__ __half g_W1h[(size_t)MM * DIN];
__device__ __half g_Wouth[(size_t)OUTN * MM];
__device__ __half g_Wbh[(size_t)CC * SS * SS * SS];
__device__ __half g_h1h[(size_t)BB * MM];
__device__ __half g_zh[(size_t)BB * MM];

// ---------------------------------------------------------------------------
// Low-level helpers
// ---------------------------------------------------------------------------
__device__ __forceinline__ uint32_t smem_u32(const void* p) {
    uint32_t a;
    asm("{ .reg .u64 t; cvta.to.shared.u64 t, %1; cvt.u32.u64 %0, t; }"
        : "=r"(a) : "l"(p));
    return a;
}

#define CP16(dst, src) \
    asm volatile("cp.async.cg.shared.global [%0], [%1], 16;" \
                 :: "r"(dst), "l"(src) : "memory")
#define CP16P(dst, src, nbytes) \
    asm volatile("cp.async.cg.shared.global [%0], [%1], 16, %2;" \
                 :: "r"(dst), "l"(src), "r"(nbytes) : "memory")
#define CP_COMMIT() asm volatile("cp.async.commit_group;" ::: "memory")
#define CP_WAIT0()  asm volatile("cp.async.wait_group 0;" ::: "memory")
#define CP_WAIT1()  asm volatile("cp.async.wait_group 1;" ::: "memory")

#define LDX4(r0, r1, r2, r3, addr) \
    asm volatile("ldmatrix.sync.aligned.m8n8.x4.shared.b16 {%0,%1,%2,%3}, [%4];" \
                 : "=r"(r0), "=r"(r1), "=r"(r2), "=r"(r3) : "r"(addr))

#define MMAH(d0, d1, d2, d3, a0, a1, a2, a3, b0, b1) \
    asm volatile("mma.sync.aligned.m16n8k16.row.col.f32.f16.f16.f32 " \
                 "{%0,%1,%2,%3}, {%4,%5,%6,%7}, {%8,%9}, {%0,%1,%2,%3};" \
                 : "+f"(d0), "+f"(d1), "+f"(d2), "+f"(d3) \
                 : "r"(a0), "r"(a1), "r"(a2), "r"(a3), "r"(b0), "r"(b1))

// ---------------------------------------------------------------------------
// fp32 -> fp16 converts (paired, independent sizes per grid.y)
// ---------------------------------------------------------------------------
__global__ __launch_bounds__(256)
void cvt2_fp16(const float* __restrict__ in0, __half* __restrict__ out0, int n4a,
               const float* __restrict__ in1, __half* __restrict__ out1, int n4b)
{
    int i = blockIdx.x * blockDim.x + threadIdx.x;
    const float* in = blockIdx.y ? in1 : in0;
    __half* out = blockIdx.y ? out1 : out0;
    int n4 = blockIdx.y ? n4b : n4a;
    if (i >= n4) return;
    float4 v = ((const float4*)in)[i];
    __half2 a = __halves2half2(__float2half(v.x), __float2half(v.y));
    __half2 b = __halves2half2(__float2half(v.z), __float2half(v.w));
    uint2 o;
    o.x = *(uint32_t*)&a; o.y = *(uint32_t*)&b;
    ((uint2*)out)[i] = o;
}

// ---------------------------------------------------------------------------
// 1-product fp16 NT GEMM core: CTA 128x128xBK64, 3-stage, 2 CTAs/SM,
// 256 threads (8 warps, warp tile 64x32), single sync per K-iter.
// ---------------------------------------------------------------------------
#define BK 64
#define STG1 32768            // A 16K | B 16K
#define SMEM1 (3 * STG1)      // 96K

__device__ __forceinline__ void issue1(
    uint32_t sbase, int stage,
    const __half* __restrict__ A, const __half* __restrict__ B,
    int m0, int n0, int k0, int N, int K, int tid)
{
    uint32_t st = sbase + stage * STG1;
#pragma unroll
    for (int i = 0; i < 4; ++i) {
        int idx = tid + i * 256;
        int r = idx >> 3;
        int c = idx & 7;
        uint32_t dst = (uint32_t)(r * 128 + ((c ^ (r & 7)) << 4));
        CP16(st + dst, (const char*)(A + (size_t)(m0 + r) * K + k0 + c * 8));
        int n = n0 + r;
        int pred = (n < N) ? 16 : 0;
        int ncl = (n < N) ? n : (N - 1);
        CP16P(st + 16384 + dst, (const char*)(B + (size_t)ncl * K + k0 + c * 8), pred);
    }
    CP_COMMIT();
}

__device__ __forceinline__ void gemm1_mainloop(
    uint32_t sb, const __half* A, const __half* B,
    int m0, int n0, int N, int K, int tid, float d[4][4][4])
{
    const int l   = tid & 31;
    const int wid = tid >> 5;
    const int wm  = wid & 1;
    const int wn  = wid >> 1;
    const int niter = K / BK;

    const uint32_t aRow  = (uint32_t)(wm * 64 + (l & 15));
    const uint32_t aXor  = aRow & 7;
    const uint32_t aHalf = (uint32_t)(l >> 4);
    const uint32_t bRow  = (uint32_t)(wn * 32 + (l & 7) + ((l >> 4) << 3));
    const uint32_t bXor  = bRow & 7;
    const uint32_t bHalf = (uint32_t)((l >> 3) & 1);

    issue1(sb, 0, A, B, m0, n0, 0, N, K, tid);
    if (niter > 1) issue1(sb, 1, A, B, m0, n0, BK, N, K, tid);

    for (int it = 0; it < niter; ++it) {
        if (it + 1 < niter) CP_WAIT1(); else CP_WAIT0();
        __syncthreads();
        if (it + 2 < niter)
            issue1(sb, (it + 2) % 3, A, B, m0, n0, (it + 2) * BK, N, K, tid);

        const uint32_t st = sb + (it % 3) * STG1;
        const uint32_t sA = st;
        const uint32_t sB = st + 16384;

#pragma unroll
        for (int kk = 0; kk < 4; ++kk) {
            uint32_t ah[4][4], bh[2][4];
            const uint32_t ach = (((2 * kk + aHalf) ^ aXor) << 4);
            const uint32_t bch = (((2 * kk + bHalf) ^ bXor) << 4);
#pragma unroll
            for (int mg = 0; mg < 4; ++mg) {
                uint32_t off = (aRow + mg * 16) * 128 + ach;
                LDX4(ah[mg][0], ah[mg][1], ah[mg][2], ah[mg][3], sA + off);
            }
#pragma unroll
            for (int bq = 0; bq < 2; ++bq) {
                uint32_t off = (bRow + bq * 16) * 128 + bch;
                LDX4(bh[bq][0], bh[bq][1], bh[bq][2], bh[bq][3], sB + off);
            }
#pragma unroll
            for (int mg = 0; mg < 4; ++mg) {
#pragma unroll
                for (int bq = 0; bq < 2; ++bq) {
#pragma unroll
                    for (int hh = 0; hh < 2; ++hh) {
                        float* dd = d[mg][bq * 2 + hh];
                        MMAH(dd[0], dd[1], dd[2], dd[3],
                             ah[mg][0], ah[mg][1], ah[mg][2], ah[mg][3],
                             bh[bq][2 * hh], bh[bq][2 * hh + 1]);
                    }
                }
            }
        }
    }
}

// Merged input GEMMs: blockIdx.z=0 -> h0 fp32; z=1 -> h1 fp16.
__global__ __launch_bounds__(256, 2)
void tc_gemm_in(const __half* __restrict__ A0, const __half* __restrict__ A1,
                const __half* __restrict__ B0, const __half* __restrict__ B1,
                const float* __restrict__ bias0, const float* __restrict__ bias1,
                float* __restrict__ C0, __half* __restrict__ C1,
                int N, int K)
{
    extern __shared__ __align__(128) char smem[];
    const uint32_t sb = smem_u32(smem);
    const int tid = threadIdx.x;
    const int which = blockIdx.z;
    const int m0 = blockIdx.y * 128;
    const int n0 = blockIdx.x * 128;

    const __half* A   = which ? A1 : A0;
    const __half* B   = which ? B1 : B0;
    const float* bias = which ? bias1 : bias0;

    float d[4][4][4];
#pragma unroll
    for (int mg = 0; mg < 4; ++mg)
#pragma unroll
        for (int ng = 0; ng < 4; ++ng)
#pragma unroll
            for (int e = 0; e < 4; ++e) d[mg][ng][e] = 0.0f;

    gemm1_mainloop(sb, A, B, m0, n0, N, K, tid, d);

    const int l  = tid & 31;
    const int wm = (tid >> 5) & 1;
    const int wn = tid >> 6;
#pragma unroll
    for (int mg = 0; mg < 4; ++mg) {
#pragma unroll
        for (int ng = 0; ng < 4; ++ng) {
            int m = m0 + wm * 64 + mg * 16 + (l >> 2);
            int n = n0 + wn * 32 + ng * 8 + 2 * (l & 3);
            if (n < N) {
                float v0 = d[mg][ng][0] + bias[n];
                float v1 = d[mg][ng][1] + bias[n + 1];
                float v2 = d[mg][ng][2] + bias[n];
                float v3 = d[mg][ng][3] + bias[n + 1];
                if (!which) {
                    *(float2*)&C0[(size_t)m * N + n] = make_float2(v0, v1);
                    *(float2*)&C0[(size_t)(m + 8) * N + n] = make_float2(v2, v3);
                } else {
                    *(__half2*)&C1[(size_t)m * N + n] =
                        __halves2half2(__float2half(v0), __float2half(v1));
                    *(__half2*)&C1[(size_t)(m + 8) * N + n] =
                        __halves2half2(__float2half(v2), __float2half(v3));
                }
            }
        }
    }
}

// Out GEMM: fp32 output
__global__ __launch_bounds__(256, 2)
void tc_gemm_out(const __half* __restrict__ A, const __half* __restrict__ B,
                 const float* __restrict__ bias, float* __restrict__ C,
                 int N, int K)
{
    extern __shared__ __align__(128) char smem[];
    const uint32_t sb = smem_u32(smem);
    const int tid = threadIdx.x;
    const int m0 = blockIdx.y * 128;
    const int n0 = blockIdx.x * 128;

    float d[4][4][4];
#pragma unroll
    for (int mg = 0; mg < 4; ++mg)
#pragma unroll
        for (int ng = 0; ng < 4; ++ng)
#pragma unroll
            for (int e = 0; e < 4; ++e) d[mg][ng][e] = 0.0f;

    gemm1_mainloop(sb, A, B, m0, n0, N, K, tid, d);

    const int l  = tid & 31;
    const int wm = (tid >> 5) & 1;
    const int wn = tid >> 6;
#pragma unroll
    for (int mg = 0; mg < 4; ++mg) {
#pragma unroll
        for (int ng = 0; ng < 4; ++ng) {
            int m = m0 + wm * 64 + mg * 16 + (l >> 2);
            int n = n0 + wn * 32 + ng * 8 + 2 * (l & 3);
            if (n < N) {
                float v0 = d[mg][ng][0] + bias[n];
                float v1 = d[mg][ng][1] + bias[n + 1];
                float v2 = d[mg][ng][2] + bias[n];
                float v3 = d[mg][ng][3] + bias[n + 1];
                *(float2*)&C[(size_t)m * N + n] = make_float2(v0, v1);
                *(float2*)&C[(size_t)(m + 8) * N + n] = make_float2(v2, v3);
            }
        }
    }
}

// ---------------------------------------------------------------------------
// Fused bilinear (fp16 1-product), 2 CTAs/SM layout [R16]:
// CTA = (c, 128-batch block); 8 warps x 16 b; 2 q's per qp sequential.
// Output: raw z (no bias) truncated to fp16 -> zT16[feat][b].
// ---------------------------------------------------------------------------
#define WB_PITCH 176
#define H1_PITCH 176
#define H0_PITCHB 336
#define H0_PITCHF 84
#define SH1B 28160
#define SH0B 50688
#define BIL_SMEM 93696

__device__ __forceinline__ void issue_wb(
    uint32_t sb, const __half* __restrict__ Wbh, int c, int qp, int tid)
{
    const size_t wb_base = (size_t)c * (SS * SS * SS) + (size_t)(qp * 2) * (SS * SS);
#pragma unroll
    for (int i = 0; i < 7; ++i) {
        int idx = tid + i * 256;
        if (idx < 1600) {
            int row = idx / 10, ch = idx % 10;
            size_t src = wb_base + (size_t)(row / 80) * (SS * SS)
                       + (size_t)(row % 80) * SS + ch * 8;
            CP16(sb + row * WB_PITCH + ch * 16, (const char*)(Wbh + src));
        }
    }
    CP_COMMIT();
}

__global__ __launch_bounds__(256, 2)
void bilq_kernel(const __half* __restrict__ Wbh,
                 const __half* __restrict__ h1h,
                 const float* __restrict__ h0g,
                 __half* __restrict__ zT16)
{
    extern __shared__ __align__(128) char smem[];
    const uint32_t sb = smem_u32(smem);
    const int tid = threadIdx.x;
    const int l   = tid & 31;
    const int wn  = tid >> 5;
    const int c   = blockIdx.y;
    const int b0  = blockIdx.x * 128;

#pragma unroll
    for (int i = 0; i < 5; ++i) {
        int idx = tid + i * 256;
        int r = idx / 10, ch = idx % 10;
        size_t src = (size_t)(b0 + r) * MM + c * SS + ch * 8;
        CP16(sb + SH1B + r * H1_PITCH + ch * 16, (const char*)(h1h + src));
    }
#pragma unroll
    for (int i = 0; i < 10; ++i) {
        int idx = tid + i * 256;
        int r = idx / 20, ch = idx % 20;
        size_t src = (size_t)(b0 + r) * MM + c * SS + ch * 4;
        CP16(sb + SH0B + r * H0_PITCHB + ch * 16, (const char*)(h0g + src));
    }
    issue_wb(sb, Wbh, c, 0, tid);

    const uint32_t aHalf = (uint32_t)(l >> 4);
    const uint32_t bRow  = (uint32_t)(wn * 16 + (l & 7) + ((l >> 4) << 3));
    const uint32_t bHalf = (uint32_t)((l >> 3) & 1);
    const uint32_t sB = sb + SH1B;
    const float* h0s = (const float*)(smem + SH0B);

    for (int qp = 0; qp < 40; ++qp) {
        CP_WAIT0();
        __syncthreads();

#pragma unroll
        for (int ql = 0; ql < 2; ++ql) {
            const uint32_t aRowOff = (uint32_t)(ql * 80 + (l & 15)) * WB_PITCH;

            float d[5][2][4];
#pragma unroll
            for (int mt = 0; mt < 5; ++mt)
#pragma unroll
                for (int nt = 0; nt < 2; ++nt)
#pragma unroll
                    for (int e = 0; e < 4; ++e) d[mt][nt][e] = 0.0f;

#pragma unroll
            for (int kk = 0; kk < 5; ++kk) {
                uint32_t ah[5][4], bh[4];
                const uint32_t aco = ((2 * kk + aHalf) << 4);
                const uint32_t bco = ((2 * kk + bHalf) << 4);
#pragma unroll
                for (int mt = 0; mt < 5; ++mt) {
                    uint32_t off = aRowOff + mt * 16 * WB_PITCH + aco;
                    LDX4(ah[mt][0], ah[mt][1], ah[mt][2], ah[mt][3], sb + off);
                }
                LDX4(bh[0], bh[1], bh[2], bh[3],
                     sB + bRow * H1_PITCH + bco);
#pragma unroll
                for (int mt = 0; mt < 5; ++mt) {
#pragma unroll
                    for (int hh = 0; hh < 2; ++hh) {
                        float* dd = d[mt][hh];
                        MMAH(dd[0], dd[1], dd[2], dd[3],
                             ah[mt][0], ah[mt][1], ah[mt][2], ah[mt][3],
                             bh[2 * hh], bh[2 * hh + 1]);
                    }
                }
            }

            float p4[4];
#pragma unroll
            for (int i = 0; i < 4; ++i) p4[i] = 0.0f;
#pragma unroll
            for (int mt = 0; mt < 5; ++mt) {
#pragma unroll
                for (int e = 0; e < 4; ++e) {
                    int s = mt * 16 + (l >> 2) + 8 * (e >> 1);
#pragma unroll
                    for (int nt = 0; nt < 2; ++nt) {
                        int bl_ = wn * 16 + nt * 8 + 2 * (l & 3) + (e & 1);
                        p4[nt * 2 + (e & 1)] += d[mt][nt][e] * h0s[bl_ * H0_PITCHF + s];
                    }
                }
            }
#pragma unroll
            for (int pi = 0; pi < 4; ++pi) {
                float v = p4[pi];
                v += __shfl_xor_sync(0xffffffffu, v, 4);
                v += __shfl_xor_sync(0xffffffffu, v, 8);
                v += __shfl_xor_sync(0xffffffffu, v, 16);
                p4[pi] = v;
            }
            if (l < 4) {
                int feat = c * SS + qp * 2 + ql;
                __half* dst = zT16 + (size_t)feat * BB + b0 + wn * 16 + 2 * l;
                *(__half2*)dst =
                    __halves2half2(__float2half(p4[0]), __float2half(p4[1]));
                *(__half2*)(dst + 8) =
                    __halves2half2(__float2half(p4[2]), __float2half(p4[3]));
            }
        }

        __syncthreads();
        if (qp + 1 < 40)
            issue_wb(sb, Wbh, c, qp + 1, tid);
    }
}

// ---------------------------------------------------------------------------
// norm: v = fp32(zT16) + bb; scale = 1/max(sqrt(sum|v|),eps);
// zh = fp16(signed_sqrt(v) * scale).  CTA = (c, 256-b block), 2 CTAs/SM.
// ---------------------------------------------------------------------------
#define NRM_ZS 0              // [80][264] fp16  = 42240 B
#define NRM_ZO 42240          // [256][84] fp16  = 43008 B
#define NRM_BB 85248          // 80 fp32 = 320 B
#define NRM_SMEM 85568

__global__ __launch_bounds__(256)
void norm_kernel(const __half* __restrict__ zT16, const float* __restrict__ bbv,
                 __half* __restrict__ zh)
{
    extern __shared__ __align__(128) char smem[];
    __half* zs = (__half*)(smem + NRM_ZS);
    __half* zo = (__half*)(smem + NRM_ZO);
    float* bbs = (float*)(smem + NRM_BB);
    const int tid = threadIdx.x;
    const int c = blockIdx.y;
    const int b0 = blockIdx.x * 256;

    if (tid < 80) bbs[tid] = bbv[c * SS + tid];
    // load 80 q-rows x 256 halfs (512B each), coalesced
#pragma unroll
    for (int i = 0; i < 10; ++i) {
        int idx = tid + i * 256;        // 2560 = 80 x 32 chunks
        int r = idx >> 5, ch = idx & 31;
        *(uint4*)&zs[r * 264 + ch * 8] =
            *(const uint4*)&zT16[(size_t)(c * SS + r) * BB + b0 + ch * 8];
    }
    __syncthreads();

    // each thread owns one b column
    float s = 0.0f;
#pragma unroll 4
    for (int q = 0; q < SS; ++q)
        s += fabsf(__half2float(zs[q * 264 + tid]) + bbs[q]);
    const float sc = 1.0f / fmaxf(sqrtf(s), 1e-12f);
#pragma unroll 4
    for (int q = 0; q < SS; ++q) {
        float v = __half2float(zs[q * 264 + tid]) + bbs[q];
        zo[tid * 84 + q] = __float2half(copysignf(sqrtf(fabsf(v)), v) * sc);
    }
    __syncthreads();

    // store 256 b-rows x 80 halfs (160B each) via uint2
#pragma unroll
    for (int i = 0; i < 20; ++i) {
        int idx = tid + i * 256;        // 5120 = 256 x 20 chunks
        int r = idx / 20, ch = idx % 20;
        *(uint2*)&zh[(size_t)(b0 + r) * MM + c * SS + ch * 4] =
            *(uint2*)((char*)zo + r * 168 + ch * 8);
    }
}

// ---------------------------------------------------------------------------
// launch
// ---------------------------------------------------------------------------
extern "C" void kernel_launch(void* const* d_in, const int* in_sizes, int n_in,
                              void* d_out, int out_size)
{
    (void)in_sizes; (void)n_in; (void)out_size;
    const float* x0   = (const float*)d_in[0];
    const float* x1   = (const float*)d_in[1];
    const float* W0   = (const float*)d_in[2];
    const float* b0   = (const float*)d_in[3];
    const float* W1   = (const float*)d_in[4];
    const float* b1   = (const float*)d_in[5];
    const float* Wb   = (const float*)d_in[6];
    const float* bb   = (const float*)d_in[7];
    const float* Wout = (const float*)d_in[8];
    const float* bout = (const float*)d_in[9];
    float* out = (float*)d_out;

    float* h0p;
    cudaGetSymbolAddress((void**)&h0p, g_h0);
    void *x0h, *x1h, *W0h, *W1h, *Woh, *Wbh, *h1h, *zh, *zT16;
    cudaGetSymbolAddress(&x0h, g_x0h);  cudaGetSymbolAddress(&x1h, g_x1h);
    cudaGetSymbolAddress(&W0h, g_W0h);  cudaGetSymbolAddress(&W1h, g_W1h);
    cudaGetSymbolAddress(&Woh, g_Wouth);
    cudaGetSymbolAddress(&Wbh, g_Wbh);
    cudaGetSymbolAddress(&h1h, g_h1h);
    cudaGetSymbolAddress(&zh, g_zh);
    cudaGetSymbolAddress(&zT16, g_zT16);

    cudaFuncSetAttribute(tc_gemm_in, cudaFuncAttributeMaxDynamicSharedMemorySize, SMEM1);
    cudaFuncSetAttribute(tc_gemm_out, cudaFuncAttributeMaxDynamicSharedMemorySize, SMEM1);
    cudaFuncSetAttribute(bilq_kernel, cudaFuncAttributeMaxDynamicSharedMemorySize, BIL_SMEM);
    cudaFuncSetAttribute(norm_kernel, cudaFuncAttributeMaxDynamicSharedMemorySize, NRM_SMEM);

    // converts (3 launches)
    {
        int n4x = BB * DIN / 4;
        dim3 g((n4x + 255) / 256, 2);
        cvt2_fp16<<<g, 256>>>(x0, (__half*)x0h, n4x, x1, (__half*)x1h, n4x);

        int n4w = MM * DIN / 4;
        dim3 g2((n4w + 255) / 256, 2);
        cvt2_fp16<<<g2, 256>>>(W0, (__half*)W0h, n4w, W1, (__half*)W1h, n4w);

        int n4wb = CC * SS * SS * SS / 4;
        int n4wo = OUTN * MM / 4;
        int nmax = n4wb > n4wo ? n4wb : n4wo;
        dim3 g3((nmax + 255) / 256, 2);
        cvt2_fp16<<<g3, 256>>>(Wb, (__half*)Wbh, n4wb, Wout, (__half*)Woh, n4wo);
    }

    // merged input GEMMs (1-product)
    {
        dim3 grid((MM + 127) / 128, BB / 128, 2);
        tc_gemm_in<<<grid, 256, SMEM1>>>(
            (const __half*)x0h, (const __half*)x1h,
            (const __half*)W0h, (const __half*)W1h,
            b0, b1, h0p, (__half*)h1h, MM, DIN);
    }

    // fused bilinear -> zT16 (128-b CTAs, 2 CTAs/SM)
    {
        dim3 grid(BB / 128, CC);
        bilq_kernel<<<grid, 256, BIL_SMEM>>>(
            (const __half*)Wbh, (const __half*)h1h, h0p, (__half*)zT16);
    }

    // bias + signed sqrt + normalize -> fp16 z
    {
        dim3 grid(BB / 256, CC);
        norm_kernel<<<grid, 256, NRM_SMEM>>>(
            (const __half*)zT16, bb, (__half*)zh);
    }

    // out = z @ Wout^T + bout (1-product)
    {
        dim3 grid((OUTN + 127) / 128, BB / 128);
        tc_gemm_out<<<grid, 256, SMEM1>>>(
            (const __half*)zh, (const __half*)Woh, bout, out, OUTN, MM);
    }
}